// round 14
// baseline (speedup 1.0000x reference)
#include <cuda_runtime.h>
#include <cuda_bf16.h>
#include <math.h>
#include <stdint.h>

#define LQ 1600
#define CD 256
#define NH 8
#define HD 32
#define DFF 1024
#define H2D 40
#define W2D 40
#define WS 15
#define WSQ 225
#define PADR 7
#define SCALE 0.17677669529663687f  // 1/sqrt(32)

#define BQ 64
#define BK 64
#define LTW 22
#define LTWW (LTW * LTW)  // 484

// GEMM chunking (BM=64, BN=64, KC=128)
#define KC 128
#define KPP 68
#define GSEG (64 * KPP)

// preconverted weight segment offsets (in bf16x2 pairs)
#define OFF_QKV  0         // [768,256] = wq | wk | wv
#define OFF_WO   98304
#define OFF_WQV  131072
#define OFF_WID  196608
#define OFF_LTST 230400
#define OFF_W1   295936
#define OFF_W2   427008
#define TOTPAIRS 558080

// ---------------- scratch (device globals; no allocation) ----------------
__device__ float g_qkv[LQ * 768];    // [q | k | v]
__device__ float g_cat[LQ * 512];
__device__ float g_tgt1[LQ * CD];
__device__ float g_qv[LQ * 512];
__device__ float g_idkv[LQ * 264];
__device__ float g_tgt2[LQ * CD];
__device__ float g_x1[LQ * DFF];
__device__ float g_x2[LQ * DFF];
__device__ float g_gnacc[64];
__device__ float g_ln1acc[LQ * 2];
__device__ float g_ln2acc[LQ * 2];
__device__ float g_ln3acc[LQ * 2];
__device__ __align__(16) uint32_t g_whi[TOTPAIRS];
__device__ __align__(16) uint32_t g_wlo[TOTPAIRS];
__device__ float g_bqkv[768];
__device__ float g_bltst[256];

// ---------------- mma helpers ----------------
__device__ __forceinline__ void mma_bf16(float* c, const uint32_t* a, const uint32_t* b) {
    asm volatile(
        "mma.sync.aligned.m16n8k16.row.col.f32.bf16.bf16.f32 "
        "{%0,%1,%2,%3}, {%4,%5,%6,%7}, {%8,%9}, {%0,%1,%2,%3};"
        : "+f"(c[0]), "+f"(c[1]), "+f"(c[2]), "+f"(c[3])
        : "r"(a[0]), "r"(a[1]), "r"(a[2]), "r"(a[3]), "r"(b[0]), "r"(b[1]));
}

__device__ __forceinline__ uint32_t pack_bf16(float lo, float hi) {
    uint32_t r;
    asm("cvt.rn.bf16x2.f32 %0, %1, %2;" : "=r"(r) : "f"(hi), "f"(lo));
    return r;
}

__device__ __forceinline__ void split_bf16_pair(float x0, float x1, uint32_t& hi, uint32_t& lo) {
    hi = pack_bf16(x0, x1);
    float h0 = __uint_as_float(hi << 16);
    float h1 = __uint_as_float(hi & 0xffff0000u);
    lo = pack_bf16(x0 - h0, x1 - h1);
}

// ---------------- per-row sum/sumsq (for fused LayerNorm) ----------------
__global__ __launch_bounds__(256) void row_stats(const float* __restrict__ in,
                                                 float* __restrict__ acc) {
    int row = blockIdx.x * 8 + (threadIdx.x >> 5);
    int lane = threadIdx.x & 31;
    const float* p = in + (size_t)row * CD + lane * 8;
    float4 a = *reinterpret_cast<const float4*>(p);
    float4 b = *reinterpret_cast<const float4*>(p + 4);
    float s = (a.x + a.y) + (a.z + a.w) + (b.x + b.y) + (b.z + b.w);
    float ss = a.x * a.x + a.y * a.y + a.z * a.z + a.w * a.w +
               b.x * b.x + b.y * b.y + b.z * b.z + b.w * b.w;
#pragma unroll
    for (int o = 16; o; o >>= 1) {
        s += __shfl_xor_sync(0xffffffffu, s, o);
        ss += __shfl_xor_sync(0xffffffffu, ss, o);
    }
    if (!lane) {
        acc[row * 2] = s;
        acc[row * 2 + 1] = ss;
    }
}

// ---------------- weight pre-conversion (once per launch) ----------------
__global__ void conv_weights(
        const float* __restrict__ wq, const float* __restrict__ wk,
        const float* __restrict__ wv, const float* __restrict__ wo,
        const float* __restrict__ wqv, const float* __restrict__ wid,
        const float* __restrict__ wlt, const float* __restrict__ wst,
        const float* __restrict__ w1, const float* __restrict__ w2,
        const float* __restrict__ bq, const float* __restrict__ bk,
        const float* __restrict__ bv, const float* __restrict__ blt,
        const float* __restrict__ bst) {
    int p = blockIdx.x * 256 + threadIdx.x;
    if (p < 256) {
        g_bqkv[p] = bq[p];
        g_bqkv[256 + p] = bk[p];
        g_bqkv[512 + p] = bv[p];
        g_bltst[p] = blt[p] + bst[p];
    }
    if (p < 64) g_gnacc[p] = 0.f;
    if (p < LQ * 2) {
        g_ln2acc[p] = 0.f;
        g_ln3acc[p] = 0.f;
    }
    if (p >= TOTPAIRS) return;
    const float* src;
    int idx;
    if (p < OFF_WO) {
        src = (p < 32768) ? wq : ((p < 65536) ? wk : wv);
        idx = (p & 32767) * 2;
    } else if (p < OFF_WQV) { src = wo; idx = (p - OFF_WO) * 2; }
    else if (p < OFF_WID) { src = wqv; idx = (p - OFF_WQV) * 2; }
    else if (p < OFF_LTST) { src = wid; idx = (p - OFF_WID) * 2; }
    else if (p < OFF_W1) {
        int lp = p - OFF_LTST;
        int n = lp >> 8, c = lp & 255;
        if (c < 128) { src = wlt; idx = (n * 128 + c) * 2; }
        else { src = wst; idx = (n * 128 + c - 128) * 2; }
    } else if (p < OFF_W2) { src = w1; idx = (p - OFF_W1) * 2; }
    else { src = w2; idx = (p - OFF_W2) * 2; }
    uint32_t hi, lo;
    split_bf16_pair(src[idx], src[idx + 1], hi, lo);
    g_whi[p] = hi;
    g_wlo[p] = lo;
}

// ---------------- bf16-split tensor-core GEMM (BM=64, BN=64) ----------------
// ldc: row stride of C. gnacc/lnacc: fused GroupNorm / per-row-LN stats of output.
// lnst+lng+lnb (+posp): LN (+pos add) applied to A rows during staging.
__global__ __launch_bounds__(256) void gemm_tc2(
        const float* __restrict__ A, int lda,
        const uint32_t* __restrict__ Whg, const uint32_t* __restrict__ Wlg,
        const float* __restrict__ bias, const float* __restrict__ res,
        float* __restrict__ C, int ldc, int M, int N, int K, float* __restrict__ gnacc,
        float* __restrict__ lnacc, const float* __restrict__ lnst,
        const float* __restrict__ lng, const float* __restrict__ lnb,
        const float* __restrict__ posp) {
    extern __shared__ uint32_t su[];
    uint32_t* Ah = su;
    uint32_t* Al = su + GSEG;
    uint32_t* Wh = su + 2 * GSEG;
    uint32_t* Wl = su + 3 * GSEG;
    __shared__ float gsum[8], gss2[8];

    int tid = threadIdx.x;
    int bm = blockIdx.y * 64, bn = blockIdx.x * 64;
    int wid = tid >> 5, lane = tid & 31;
    int wm = wid & 3, wn = wid >> 2;
    int g = lane >> 2, t = lane & 3;
    int m0 = wm * 16;
    int Kp = K >> 1;
    float acc[4][4] = {};

    int srow = tid >> 2, sc0 = tid & 3;
    bool wok = (bn + srow) < N;
    const float* Ap = A + (size_t)(bm + srow) * lda;
    const uint32_t* Whp = Whg + (size_t)(wok ? bn + srow : 0) * Kp;
    const uint32_t* Wlp = Wlg + (size_t)(wok ? bn + srow : 0) * Kp;

    float lnm = 0.f, lnr = 1.f;
    if (lnst) {
        float s = lnst[(bm + srow) * 2], ss = lnst[(bm + srow) * 2 + 1];
        lnm = s * (1.0f / CD);
        float var = ss * (1.0f / CD) - lnm * lnm;
        lnr = rsqrtf(var + 1e-5f);
    }

    float4 pa[8];
    uint4 pwh[4], pwl[4];
    const uint4 z4 = make_uint4(0, 0, 0, 0);

#define LOADCHUNK(k0)                                                          \
    {                                                                          \
        int kp0 = (k0) >> 1;                                                   \
        _Pragma("unroll")                                                      \
        for (int i = 0; i < 4; i++) {                                          \
            int cA = (k0) + (2 * sc0 + 8 * i) * 4;                             \
            pa[2 * i] = *reinterpret_cast<const float4*>(Ap + cA);             \
            pa[2 * i + 1] = *reinterpret_cast<const float4*>(Ap + cA + 4);     \
            int pp = kp0 + (sc0 + 4 * i) * 4;                                  \
            pwh[i] = wok ? *reinterpret_cast<const uint4*>(Whp + pp) : z4;     \
            pwl[i] = wok ? *reinterpret_cast<const uint4*>(Wlp + pp) : z4;     \
        }                                                                      \
    }

    LOADCHUNK(0)

    for (int k0 = 0; k0 < K; k0 += KC) {
        if (k0) __syncthreads();
#pragma unroll
        for (int i = 0; i < 4; i++) {
            float e[8] = {pa[2 * i].x, pa[2 * i].y, pa[2 * i].z, pa[2 * i].w,
                          pa[2 * i + 1].x, pa[2 * i + 1].y, pa[2 * i + 1].z, pa[2 * i + 1].w};
            if (lnst) {
                int cb = k0 + (2 * sc0 + 8 * i) * 4;
                float4 g0 = *reinterpret_cast<const float4*>(lng + cb);
                float4 g1 = *reinterpret_cast<const float4*>(lng + cb + 4);
                float4 b0 = *reinterpret_cast<const float4*>(lnb + cb);
                float4 b1 = *reinterpret_cast<const float4*>(lnb + cb + 4);
                float gv[8] = {g0.x, g0.y, g0.z, g0.w, g1.x, g1.y, g1.z, g1.w};
                float bv[8] = {b0.x, b0.y, b0.z, b0.w, b1.x, b1.y, b1.z, b1.w};
#pragma unroll
                for (int j = 0; j < 8; j++)
                    e[j] = (e[j] - lnm) * lnr * gv[j] + bv[j];
                if (posp) {
                    const float* pp2 = posp + (size_t)(bm + srow) * CD + cb;
                    float4 p0 = *reinterpret_cast<const float4*>(pp2);
                    float4 p1 = *reinterpret_cast<const float4*>(pp2 + 4);
                    e[0] += p0.x; e[1] += p0.y; e[2] += p0.z; e[3] += p0.w;
                    e[4] += p1.x; e[5] += p1.y; e[6] += p1.z; e[7] += p1.w;
                }
            }
            uint32_t h0, l0, h1, l1, h2, l2, h3, l3;
            split_bf16_pair(e[0], e[1], h0, l0);
            split_bf16_pair(e[2], e[3], h1, l1);
            split_bf16_pair(e[4], e[5], h2, l2);
            split_bf16_pair(e[6], e[7], h3, l3);
            int pp = srow * KPP + (sc0 + 4 * i) * 4;
            *reinterpret_cast<uint4*>(&Ah[pp]) = make_uint4(h0, h1, h2, h3);
            *reinterpret_cast<uint4*>(&Al[pp]) = make_uint4(l0, l1, l2, l3);
            *reinterpret_cast<uint4*>(&Wh[pp]) = pwh[i];
            *reinterpret_cast<uint4*>(&Wl[pp]) = pwl[i];
        }
        __syncthreads();
        if (k0 + KC < K) LOADCHUNK(k0 + KC)

#pragma unroll
        for (int ks = 0; ks < KC / 16; ks++) {
            int kb = ks * 8 + t;
            uint32_t ah[4], al[4];
            ah[0] = Ah[(m0 + g) * KPP + kb];
            ah[1] = Ah[(m0 + 8 + g) * KPP + kb];
            ah[2] = Ah[(m0 + g) * KPP + kb + 4];
            ah[3] = Ah[(m0 + 8 + g) * KPP + kb + 4];
            al[0] = Al[(m0 + g) * KPP + kb];
            al[1] = Al[(m0 + 8 + g) * KPP + kb];
            al[2] = Al[(m0 + g) * KPP + kb + 4];
            al[3] = Al[(m0 + 8 + g) * KPP + kb + 4];
#pragma unroll
            for (int nt = 0; nt < 4; nt++) {
                int nr = wn * 32 + nt * 8 + g;
                uint32_t bh[2] = {Wh[nr * KPP + kb], Wh[nr * KPP + kb + 4]};
                uint32_t bl[2] = {Wl[nr * KPP + kb], Wl[nr * KPP + kb + 4]};
                mma_bf16(acc[nt], ah, bh);
                mma_bf16(acc[nt], ah, bl);
                mma_bf16(acc[nt], al, bh);
            }
        }
    }

    int mo = bm + m0 + g;
    float ts = 0.f, tss = 0.f;
    float rs0 = 0.f, rq0 = 0.f, rs1 = 0.f, rq1 = 0.f;
    if (bn + 64 <= N) {
#pragma unroll
        for (int nt = 0; nt < 4; nt++) {
            int n = bn + wn * 32 + nt * 8 + 2 * t;
            float2 bv = *reinterpret_cast<const float2*>(bias + n);
            size_t o0 = (size_t)mo * ldc + n;
            size_t o1 = (size_t)(mo + 8) * ldc + n;
            float2 r0 = make_float2(acc[nt][0] + bv.x, acc[nt][1] + bv.y);
            float2 r1 = make_float2(acc[nt][2] + bv.x, acc[nt][3] + bv.y);
            if (res) {
                float2 e0 = *reinterpret_cast<const float2*>(res + o0);
                float2 e1 = *reinterpret_cast<const float2*>(res + o1);
                r0.x += e0.x; r0.y += e0.y; r1.x += e1.x; r1.y += e1.y;
            }
            if (gnacc) {
                ts += (r0.x + r0.y) + (r1.x + r1.y);
                tss += r0.x * r0.x + r0.y * r0.y + r1.x * r1.x + r1.y * r1.y;
            }
            if (lnacc) {
                rs0 += r0.x + r0.y;
                rq0 += r0.x * r0.x + r0.y * r0.y;
                rs1 += r1.x + r1.y;
                rq1 += r1.x * r1.x + r1.y * r1.y;
            }
            *reinterpret_cast<float2*>(C + o0) = r0;
            *reinterpret_cast<float2*>(C + o1) = r1;
        }
    } else {
#pragma unroll
        for (int nt = 0; nt < 4; nt++) {
            int n = bn + wn * 32 + nt * 8 + 2 * t;
#pragma unroll
            for (int e = 0; e < 2; e++) {
                if (n + e >= N) continue;
                float v0 = acc[nt][e] + bias[n + e];
                float v1 = acc[nt][2 + e] + bias[n + e];
                if (res) {
                    v0 += res[(size_t)mo * ldc + n + e];
                    v1 += res[(size_t)(mo + 8) * ldc + n + e];
                }
                C[(size_t)mo * ldc + n + e] = v0;
                C[(size_t)(mo + 8) * ldc + n + e] = v1;
            }
        }
    }
    if (lnacc) {
        rs0 += __shfl_xor_sync(0xffffffffu, rs0, 1);
        rs0 += __shfl_xor_sync(0xffffffffu, rs0, 2);
        rq0 += __shfl_xor_sync(0xffffffffu, rq0, 1);
        rq0 += __shfl_xor_sync(0xffffffffu, rq0, 2);
        rs1 += __shfl_xor_sync(0xffffffffu, rs1, 1);
        rs1 += __shfl_xor_sync(0xffffffffu, rs1, 2);
        rq1 += __shfl_xor_sync(0xffffffffu, rq1, 1);
        rq1 += __shfl_xor_sync(0xffffffffu, rq1, 2);
        if (t == 0) {
            atomicAdd(&lnacc[mo * 2], rs0);
            atomicAdd(&lnacc[mo * 2 + 1], rq0);
            atomicAdd(&lnacc[(mo + 8) * 2], rs1);
            atomicAdd(&lnacc[(mo + 8) * 2 + 1], rq1);
        }
    }
    if (gnacc) {
#pragma unroll
        for (int o = 16; o; o >>= 1) {
            ts += __shfl_xor_sync(0xffffffffu, ts, o);
            tss += __shfl_xor_sync(0xffffffffu, tss, o);
        }
        if (!lane) { gsum[wid] = ts; gss2[wid] = tss; }
        __syncthreads();
        if (tid < 2) {
            float S = gsum[tid * 4] + gsum[tid * 4 + 1] + gsum[tid * 4 + 2] + gsum[tid * 4 + 3];
            float SS = gss2[tid * 4] + gss2[tid * 4 + 1] + gss2[tid * 4 + 2] + gss2[tid * 4 + 3];
            int grp = (bn >> 5) + tid;
            atomicAdd(&gnacc[grp * 2], S);
            atomicAdd(&gnacc[grp * 2 + 1], SS);
        }
    }
#undef LOADCHUNK
}

// ---------------- tensor-core flash attention (bf16 hi/lo split) ----------------
// Per-key-half independent online softmax; exact logsumexp merge in epilogue.
__global__ __launch_bounds__(256) void flash_attn_tc(
        const float* __restrict__ Q, int ldq,
        const float* __restrict__ K, int ldk,
        const float* __restrict__ V, int ldv,
        const float* __restrict__ idkv,
        float* __restrict__ O, int ldo) {
    __shared__ uint32_t Qhi[64][20], Qlo[64][20];
    __shared__ uint32_t Khi[64][20], Klo[64][20];
    __shared__ uint32_t Vthi[32][36], Vtlo[32][36];
    __shared__ float redmax[64], redsum[64];
    __shared__ float Osm[64][33];

    int h = blockIdx.y, q0 = blockIdx.x * BQ;
    int tid = threadIdx.x, wid = tid >> 5, lane = tid & 31;
    int wm = wid & 3, wn = wid >> 2;
    int g = lane >> 2, t = lane & 3;
    int m0 = wm * 16;
    int lrow = tid >> 2, lcol = (tid & 3) * 8;

    {
        const float* qp = Q + (size_t)(q0 + lrow) * ldq + h * HD + lcol;
        float4 a = *reinterpret_cast<const float4*>(qp);
        float4 b = *reinterpret_cast<const float4*>(qp + 4);
        float xv[8] = {a.x, a.y, a.z, a.w, b.x, b.y, b.z, b.w};
#pragma unroll
        for (int j = 0; j < 4; j++) {
            uint32_t hi, lo;
            split_bf16_pair(xv[2 * j] * SCALE, xv[2 * j + 1] * SCALE, hi, lo);
            Qhi[lrow][lcol / 2 + j] = hi;
            Qlo[lrow][lcol / 2 + j] = lo;
        }
    }

    float mrow[2] = {-1e30f, -1e30f}, lsum[2] = {0.f, 0.f};
    float Oacc[4][4] = {};

    for (int kt = 0; kt < LQ; kt += BK) {
        const float* kp = K + (size_t)(kt + lrow) * ldk + h * HD + lcol;
        const float* vp = V + (size_t)(kt + lrow) * ldv + h * HD + lcol;
        float4 ka = *reinterpret_cast<const float4*>(kp);
        float4 kb = *reinterpret_cast<const float4*>(kp + 4);
        float4 va = *reinterpret_cast<const float4*>(vp);
        float4 vb = *reinterpret_cast<const float4*>(vp + 4);
        float kmul = 1.f;
        float4 ia = make_float4(0.f, 0.f, 0.f, 0.f), ib = ia;
        if (idkv) {
            const float* ip = idkv + (size_t)(kt + lrow) * 264;
            kmul = 1.f + tanhf(ip[h]);
            ia = *reinterpret_cast<const float4*>(ip + 8 + h * HD + lcol);
            ib = *reinterpret_cast<const float4*>(ip + 8 + h * HD + lcol + 4);
        }
        __syncthreads();
        {
            float kv[8] = {ka.x * kmul, ka.y * kmul, ka.z * kmul, ka.w * kmul,
                           kb.x * kmul, kb.y * kmul, kb.z * kmul, kb.w * kmul};
#pragma unroll
            for (int j = 0; j < 4; j++) {
                uint32_t hi, lo;
                split_bf16_pair(kv[2 * j], kv[2 * j + 1], hi, lo);
                Khi[lrow][lcol / 2 + j] = hi;
                Klo[lrow][lcol / 2 + j] = lo;
            }
            float vv[8] = {va.x + ia.x, va.y + ia.y, va.z + ia.z, va.w + ia.w,
                           vb.x + ib.x, vb.y + ib.y, vb.z + ib.z, vb.w + ib.w};
            __nv_bfloat16* VH = reinterpret_cast<__nv_bfloat16*>(Vthi);
            __nv_bfloat16* VL = reinterpret_cast<__nv_bfloat16*>(Vtlo);
#pragma unroll
            for (int j = 0; j < 8; j++) {
                int d = lcol + j;
                float x = vv[j];
                __nv_bfloat16 hb = __float2bfloat16(x);
                VH[d * 72 + lrow] = hb;
                VL[d * 72 + lrow] = __float2bfloat16(x - __bfloat162float(hb));
            }
        }
        __syncthreads();

        float S[4][4];
#pragma unroll
        for (int nt = 0; nt < 4; nt++)
#pragma unroll
            for (int c = 0; c < 4; c++) S[nt][c] = 0.f;
#pragma unroll
        for (int kc = 0; kc < 2; kc++) {
            uint32_t ah[4], al[4];
            ah[0] = Qhi[m0 + g][kc * 8 + t];     ah[1] = Qhi[m0 + 8 + g][kc * 8 + t];
            ah[2] = Qhi[m0 + g][kc * 8 + t + 4]; ah[3] = Qhi[m0 + 8 + g][kc * 8 + t + 4];
            al[0] = Qlo[m0 + g][kc * 8 + t];     al[1] = Qlo[m0 + 8 + g][kc * 8 + t];
            al[2] = Qlo[m0 + g][kc * 8 + t + 4]; al[3] = Qlo[m0 + 8 + g][kc * 8 + t + 4];
#pragma unroll
            for (int nt = 0; nt < 4; nt++) {
                int kr = wn * 32 + nt * 8 + g;
                uint32_t bh[2] = {Khi[kr][kc * 8 + t], Khi[kr][kc * 8 + t + 4]};
                uint32_t bl[2] = {Klo[kr][kc * 8 + t], Klo[kr][kc * 8 + t + 4]};
                mma_bf16(S[nt], ah, bh);
                mma_bf16(S[nt], ah, bl);
                mma_bf16(S[nt], al, bh);
            }
        }

        float pmA = -1e30f, pmB = -1e30f;
#pragma unroll
        for (int nt = 0; nt < 4; nt++) {
            pmA = fmaxf(pmA, fmaxf(S[nt][0], S[nt][1]));
            pmB = fmaxf(pmB, fmaxf(S[nt][2], S[nt][3]));
        }
        pmA = fmaxf(pmA, __shfl_xor_sync(0xffffffffu, pmA, 1));
        pmA = fmaxf(pmA, __shfl_xor_sync(0xffffffffu, pmA, 2));
        pmB = fmaxf(pmB, __shfl_xor_sync(0xffffffffu, pmB, 1));
        pmB = fmaxf(pmB, __shfl_xor_sync(0xffffffffu, pmB, 2));
        float nmA = fmaxf(mrow[0], pmA);
        float nmB = fmaxf(mrow[1], pmB);
        float alA = __expf(mrow[0] - nmA), alB = __expf(mrow[1] - nmB);
        mrow[0] = nmA; mrow[1] = nmB;
        float psA = 0.f, psB = 0.f;
#pragma unroll
        for (int nt = 0; nt < 4; nt++) {
            S[nt][0] = __expf(S[nt][0] - nmA); S[nt][1] = __expf(S[nt][1] - nmA);
            S[nt][2] = __expf(S[nt][2] - nmB); S[nt][3] = __expf(S[nt][3] - nmB);
            psA += S[nt][0] + S[nt][1];
            psB += S[nt][2] + S[nt][3];
        }
        psA += __shfl_xor_sync(0xffffffffu, psA, 1);
        psA += __shfl_xor_sync(0xffffffffu, psA, 2);
        psB += __shfl_xor_sync(0xffffffffu, psB, 1);
        psB += __shfl_xor_sync(0xffffffffu, psB, 2);
        lsum[0] = lsum[0] * alA + psA;
        lsum[1] = lsum[1] * alB + psB;
#pragma unroll
        for (int nt = 0; nt < 4; nt++) {
            Oacc[nt][0] *= alA; Oacc[nt][1] *= alA;
            Oacc[nt][2] *= alB; Oacc[nt][3] *= alB;
        }

#pragma unroll
        for (int kc2 = 0; kc2 < 2; kc2++) {
            uint32_t ph[4], pl[4];
            split_bf16_pair(S[2 * kc2][0], S[2 * kc2][1], ph[0], pl[0]);
            split_bf16_pair(S[2 * kc2][2], S[2 * kc2][3], ph[1], pl[1]);
            split_bf16_pair(S[2 * kc2 + 1][0], S[2 * kc2 + 1][1], ph[2], pl[2]);
            split_bf16_pair(S[2 * kc2 + 1][2], S[2 * kc2 + 1][3], ph[3], pl[3]);
            int cb = wn * 16 + kc2 * 8 + t;
#pragma unroll
            for (int ntv = 0; ntv < 4; ntv++) {
                int vr = ntv * 8 + g;
                uint32_t bh[2] = {Vthi[vr][cb], Vthi[vr][cb + 4]};
                uint32_t bl[2] = {Vtlo[vr][cb], Vtlo[vr][cb + 4]};
                mma_bf16(Oacc[ntv], ph, bh);
                mma_bf16(Oacc[ntv], ph, bl);
                mma_bf16(Oacc[ntv], pl, bh);
            }
        }
    }

    if (wn == 0) {
#pragma unroll
        for (int ntv = 0; ntv < 4; ntv++) {
            int d = ntv * 8 + 2 * t;
            Osm[m0 + g][d] = Oacc[ntv][0];
            Osm[m0 + g][d + 1] = Oacc[ntv][1];
            Osm[m0 + 8 + g][d] = Oacc[ntv][2];
            Osm[m0 + 8 + g][d + 1] = Oacc[ntv][3];
        }
        if (t == 0) {
            redmax[m0 + g] = mrow[0];
            redsum[m0 + g] = lsum[0];
            redmax[m0 + 8 + g] = mrow[1];
            redsum[m0 + 8 + g] = lsum[1];
        }
    }
    __syncthreads();
    if (wn == 1) {
        float mA0 = redmax[m0 + g], lA0 = redsum[m0 + g];
        float mB0 = redmax[m0 + 8 + g], lB0 = redsum[m0 + 8 + g];
        float MA = fmaxf(mA0, mrow[0]), MB = fmaxf(mB0, mrow[1]);
        float eA0 = __expf(mA0 - MA), eA1 = __expf(mrow[0] - MA);
        float eB0 = __expf(mB0 - MB), eB1 = __expf(mrow[1] - MB);
        float invA = 1.0f / (lA0 * eA0 + lsum[0] * eA1);
        float invB = 1.0f / (lB0 * eB0 + lsum[1] * eB1);
#pragma unroll
        for (int ntv = 0; ntv < 4; ntv++) {
            int d = ntv * 8 + 2 * t;
            float* op0 = O + (size_t)(q0 + m0 + g) * ldo + h * HD + d;
            float* op1 = O + (size_t)(q0 + m0 + 8 + g) * ldo + h * HD + d;
            op0[0] = (Osm[m0 + g][d] * eA0 + Oacc[ntv][0] * eA1) * invA;
            op0[1] = (Osm[m0 + g][d + 1] * eA0 + Oacc[ntv][1] * eA1) * invA;
            op1[0] = (Osm[m0 + 8 + g][d] * eB0 + Oacc[ntv][2] * eB1) * invB;
            op1[1] = (Osm[m0 + 8 + g][d + 1] * eB0 + Oacc[ntv][3] * eB1) * invB;
        }
    }
}

// ---------------- tiled local attention with fused global-KV transform ----------------
__global__ __launch_bounds__(256) void local_attn_tile(
        const float* __restrict__ Q, int ldq,
        const float* __restrict__ qvbuf, const float* __restrict__ idkv,
        float* __restrict__ O, int ldo) {
    extern __shared__ float sm[];
    float* winK = sm;
    float* winV = sm + LTWW * 33;
    float* pb = sm + 2 * LTWW * 33;
    int h = blockIdx.y;
    int ty0 = (blockIdx.x / 5) * 8, tx0 = (blockIdx.x % 5) * 8;
    int wy0 = ty0 - PADR, wx0 = tx0 - PADR;
    int tid = threadIdx.x, w = tid >> 5, lane = tid & 31;

    for (int idx = tid; idx < LTWW * 32; idx += 256) {
        int pos = idx >> 5, d = idx & 31;
        int gy = wy0 + pos / LTW, gx = wx0 + pos % LTW;
        bool ok = ((unsigned)gy < H2D) && ((unsigned)gx < W2D);
        float kvv = 0.f, vvv = 0.f;
        if (ok) {
            size_t r = (size_t)(gy * W2D + gx);
            float ik = idkv[r * 264 + h];
            kvv = qvbuf[r * 512 + h * HD + d] * (1.0f + tanhf(ik));
            vvv = qvbuf[r * 512 + 256 + h * HD + d] + idkv[r * 264 + 8 + h * HD + d];
        }
        winK[pos * 33 + d] = kvv;
        winV[pos * 33 + d] = vvv;
    }
    __syncthreads();

    int qy = ty0 + w;
    for (int qi = 0; qi < 8; qi++) {
        int qx = tx0 + qi;
        float qv = Q[(size_t)(qy * W2D + qx) * ldq + h * HD + lane] * SCALE;
        float lg[8];
        int wi[8];
        bool val[8];
#pragma unroll
        for (int c = 0; c < 8; c++) {
            int j = c * 32 + lane;
            int jr = j / 15, jc = j - jr * 15;
            int gy2 = qy + jr - PADR, gx2 = qx + jc - PADR;
            val[c] = (j < WSQ) && ((unsigned)gy2 < H2D) && ((unsigned)gx2 < W2D);
            wi[c] = (j < WSQ) ? ((w + jr) * LTW + (qi + jc)) : 0;
            lg[c] = 0.f;
        }
#pragma unroll 8
        for (int d = 0; d < 32; d++) {
            float qd = __shfl_sync(0xffffffffu, qv, d);
#pragma unroll
            for (int c = 0; c < 8; c++)
                lg[c] = fmaf(qd, winK[wi[c] * 33 + d], lg[c]);
        }
        float mx = -1e30f;
#pragma unroll
        for (int c = 0; c < 8; c++) {
            lg[c] = val[c] ? lg[c] : -1e30f;
            mx = fmaxf(mx, lg[c]);
        }
#pragma unroll
        for (int o = 16; o; o >>= 1) mx = fmaxf(mx, __shfl_xor_sync(0xffffffffu, mx, o));
        float s = 0.f;
#pragma unroll
        for (int c = 0; c < 8; c++) {
            lg[c] = __expf(lg[c] - mx);
            s += lg[c];
        }
#pragma unroll
        for (int o = 16; o; o >>= 1) s += __shfl_xor_sync(0xffffffffu, s, o);
        float inv = 1.0f / s;
#pragma unroll
        for (int c = 0; c < 8; c++) pb[w * 264 + c * 32 + lane] = lg[c] * inv;
        __syncwarp();

        float oacc = 0.f;
        int j = 0;
#pragma unroll
        for (int jr = 0; jr < 15; jr++) {
            int base = ((w + jr) * LTW + qi) * 33 + lane;
#pragma unroll
            for (int jc = 0; jc < 15; jc++) {
                oacc = fmaf(pb[w * 264 + j], winV[base + jc * 33], oacc);
                j++;
            }
        }
        O[(size_t)(qy * W2D + qx) * ldo + h * HD + lane] = oacc;
        __syncwarp();
    }
}

// ---------------- fused GN-apply + GELU + depthwise 5x5 conv ----------------
#define DWP 144
__global__ __launch_bounds__(256) void dwconv_gn(
        const float* __restrict__ x1, const float* __restrict__ acc,
        const float* __restrict__ gg, const float* __restrict__ gb,
        const float* __restrict__ dwk, float* __restrict__ y) {
    extern __shared__ float sm[];
    float* winX = sm;
    float* wk = sm + DWP * 128;
    float* sgg = wk + 128 * 25;
    float* sgb = sgg + 128;
    float* smr = sgb + 128;
    int tile = blockIdx.x, slab = blockIdx.y;
    int ty0 = (tile / 5) * 8, tx0 = (tile % 5) * 8;
    int tid = threadIdx.x;
    int c0 = slab * 128;

    if (tid < 4) {
        int gidx = (c0 >> 5) + tid;
        const float inv = 1.0f / 51200.0f;
        float s = acc[gidx * 2], ss = acc[gidx * 2 + 1];
        float m = s * inv;
        float var = ss * inv - m * m;
        smr[tid] = m;
        smr[4 + tid] = rsqrtf(var + 1e-5f);
    }
    if (tid < 128) {
        sgg[tid] = gg[c0 + tid];
        sgb[tid] = gb[c0 + tid];
    }
    for (int i = tid; i < 128 * 25; i += 256) wk[i] = dwk[c0 * 25 + i];
    __syncthreads();

    for (int idx = tid; idx < DWP * 32; idx += 256) {
        int pos = idx >> 5, f4 = idx & 31;
        int gy = ty0 - 2 + pos / 12, gx = tx0 - 2 + pos % 12;
        bool ok = ((unsigned)gy < H2D) && ((unsigned)gx < W2D);
        float4 v = ok ? *reinterpret_cast<const float4*>(
                            x1 + (size_t)(gy * W2D + gx) * DFF + c0 + f4 * 4)
                      : make_float4(0.f, 0.f, 0.f, 0.f);
        int grp = f4 >> 3;
        float m = smr[grp], r = smr[4 + grp];
        int cl = f4 * 4;
        float e[4] = {v.x, v.y, v.z, v.w};
#pragma unroll
        for (int j = 0; j < 4; j++) {
            float t2 = (e[j] - m) * r * sgg[cl + j] + sgb[cl + j];
            e[j] = 0.5f * t2 * (1.0f + erff(t2 * 0.70710678118654752f));
        }
        float4 o = make_float4(ok ? e[0] : 0.f, ok ? e[1] : 0.f,
                               ok ? e[2] : 0.f, ok ? e[3] : 0.f);
        *reinterpret_cast<float4*>(&winX[pos * 128 + cl]) = o;
    }
    __syncthreads();

    int c = tid & 127, pg = tid >> 7;
    float wreg[25];
#pragma unroll
    for (int k = 0; k < 25; k++) wreg[k] = wk[c * 25 + k];

#pragma unroll
    for (int py = 0; py < 4; py++) {
        int oy = pg * 4 + py;
        float oac[8] = {};
#pragma unroll
        for (int dy = 0; dy < 5; dy++) {
            float rv[12];
            int rb = (oy + dy) * 12;
#pragma unroll
            for (int j = 0; j < 12; j++) rv[j] = winX[(rb + j) * 128 + c];
#pragma unroll
            for (int dx = 0; dx < 5; dx++) {
                float wv = wreg[dy * 5 + dx];
#pragma unroll
                for (int o = 0; o < 8; o++)
                    oac[o] = fmaf(rv[o + dx], wv, oac[o]);
            }
        }
#pragma unroll
        for (int o = 0; o < 8; o++)
            y[(size_t)((ty0 + oy) * W2D + tx0 + o) * DFF + c0 + c] = oac[o];
    }
}

// ---------------- host ----------------
static const int GEMM_SMEM = 4 * GSEG * (int)sizeof(uint32_t);
static const int DW_SMEM = (DWP * 128 + 128 * 25 + 256 + 8) * (int)sizeof(float);

extern "C" void kernel_launch(void* const* d_in, const int* in_sizes, int n_in,
                              void* d_out, int out_size) {
    const float* tgt = (const float*)d_in[0];
    const float* curr_id_emb = (const float*)d_in[1];
    const float* self_pos = (const float*)d_in[2];
    const float* ln1_g = (const float*)d_in[3];
    const float* ln1_b = (const float*)d_in[4];
    const float* sa_wq = (const float*)d_in[5];
    const float* sa_bq = (const float*)d_in[6];
    const float* sa_wk = (const float*)d_in[7];
    const float* sa_bk = (const float*)d_in[8];
    const float* sa_wv = (const float*)d_in[9];
    const float* sa_bv = (const float*)d_in[10];
    const float* sa_wo = (const float*)d_in[11];
    const float* sa_bo = (const float*)d_in[12];
    const float* ln2_g = (const float*)d_in[13];
    const float* ln2_b = (const float*)d_in[14];
    const float* w_qv = (const float*)d_in[15];
    const float* b_qv = (const float*)d_in[16];
    const float* w_id = (const float*)d_in[17];
    const float* b_id = (const float*)d_in[18];
    const float* lt_wo = (const float*)d_in[19];
    const float* lt_bo = (const float*)d_in[20];
    const float* st_wo = (const float*)d_in[21];
    const float* st_bo = (const float*)d_in[22];
    const float* ln3_g = (const float*)d_in[23];
    const float* ln3_b = (const float*)d_in[24];
    const float* w1 = (const float*)d_in[25];
    const float* b1 = (const float*)d_in[26];
    const float* gn_g = (const float*)d_in[27];
    const float* gn_b = (const float*)d_in[28];
    const float* dw_k = (const float*)d_in[29];
    const float* w2 = (const float*)d_in[30];
    const float* b2 = (const float*)d_in[31];
    float* out = (float*)d_out;

    float *qkv, *cat, *tgt1, *qv, *idkv, *tgt2, *x1, *x2, *gnacc;
    float *ln1acc, *ln2acc, *ln3acc, *bqkv, *bltst;
    uint32_t *whi, *wlo;
    cudaGetSymbolAddress((void**)&qkv, g_qkv);
    cudaGetSymbolAddress((void**)&cat, g_cat);
    cudaGetSymbolAddress((void**)&tgt1, g_tgt1);
    cudaGetSymbolAddress((void**)&qv, g_qv);
    cudaGetSymbolAddress((void**)&idkv, g_idkv);
    cudaGetSymbolAddress((void**)&tgt2, g_tgt2);
    cudaGetSymbolAddress((void**)&x1, g_x1);
    cudaGetSymbolAddress((void**)&x2, g_x2);
    cudaGetSymbolAddress((void**)&gnacc, g_gnacc);
    cudaGetSymbolAddress((void**)&ln1acc, g_ln1acc);
    cudaGetSymbolAddress((void**)&ln2acc, g_ln2acc);
    cudaGetSymbolAddress((void**)&ln3acc, g_ln3acc);
    cudaGetSymbolAddress((void**)&bqkv, g_bqkv);
    cudaGetSymbolAddress((void**)&bltst, g_bltst);
    cudaGetSymbolAddress((void**)&whi, g_whi);
    cudaGetSymbolAddress((void**)&wlo, g_wlo);

    const int LOCAL_SMEM = (2 * LTWW * 33 + 8 * 264) * (int)sizeof(float);

    static bool init = false;
    static cudaStream_t s1, s2;
    static cudaEvent_t evR, evW, evB, evQV, evL;
    if (!init) {
        cudaStreamCreateWithFlags(&s1, cudaStreamNonBlocking);
        cudaStreamCreateWithFlags(&s2, cudaStreamNonBlocking);
        cudaEventCreateWithFlags(&evR, cudaEventDisableTiming);
        cudaEventCreateWithFlags(&evW, cudaEventDisableTiming);
        cudaEventCreateWithFlags(&evB, cudaEventDisableTiming);
        cudaEventCreateWithFlags(&evQV, cudaEventDisableTiming);
        cudaEventCreateWithFlags(&evL, cudaEventDisableTiming);
        cudaFuncSetAttribute(local_attn_tile, cudaFuncAttributeMaxDynamicSharedMemorySize, LOCAL_SMEM);
        cudaFuncSetAttribute(gemm_tc2, cudaFuncAttributeMaxDynamicSharedMemorySize, GEMM_SMEM);
        cudaFuncSetAttribute(dwconv_gn, cudaFuncAttributeMaxDynamicSharedMemorySize, DW_SMEM);
        init = true;
    }

    auto GEMM = [&](cudaStream_t st, const float* A, int lda, int woff, const float* bias,
                    const float* res, float* C, int ldc, int M, int N, int K, float* gn,
                    float* lnacc, const float* lnst, const float* lng, const float* lnb,
                    const float* posp) {
        dim3 grid((N + 63) / 64, (M + 63) / 64);
        gemm_tc2<<<grid, 256, GEMM_SMEM, st>>>(A, lda, whi + woff, wlo + woff, bias, res, C,
                                               ldc, M, N, K, gn, lnacc, lnst, lng, lnb, posp);
    };

    // ---- fork: side stream does weight conversion + idkv GEMM ----
    cudaEventRecord(evR, 0);
    cudaStreamWaitEvent(s1, evR, 0);
    conv_weights<<<(TOTPAIRS + 255) / 256, 256, 0, s1>>>(
        sa_wq, sa_wk, sa_wv, sa_wo, w_qv, w_id, lt_wo, st_wo, w1, w2,
        sa_bq, sa_bk, sa_bv, lt_bo, st_bo);
    cudaEventRecord(evW, s1);
    GEMM(s1, curr_id_emb, CD, OFF_WID, b_id, nullptr, idkv, 264, LQ, 264, CD,
         nullptr, nullptr, nullptr, nullptr, nullptr, nullptr);
    cudaEventRecord(evB, s1);

    // ---- self-attention block: two back-to-back GEMMs into one qkv buffer ----
    // q|k uses A = ln1(x)+pos; v uses A = ln1(x). Outputs strided (ldc=768).
    row_stats<<<LQ / 8, 256>>>(tgt, ln1acc);
    cudaStreamWaitEvent(0, evW, 0);
    GEMM(0, tgt, CD, OFF_QKV, bqkv, nullptr, qkv, 768, LQ, 512, CD,
         nullptr, nullptr, ln1acc, ln1_g, ln1_b, self_pos);                  // [q|k]
    GEMM(0, tgt, CD, OFF_QKV + 65536, bqkv + 512, nullptr, qkv + 512, 768, LQ, CD, CD,
         nullptr, nullptr, ln1acc, ln1_g, ln1_b, nullptr);                   // v
    flash_attn_tc<<<dim3(LQ / BQ, NH), 256>>>(qkv, 768, qkv + 256, 768, qkv + 512, 768,
                                              nullptr, cat, 512);
    GEMM(0, cat, 512, OFF_WO, sa_bo, tgt, tgt1, 256, LQ, CD, CD,
         nullptr, ln2acc, nullptr, nullptr, nullptr, nullptr);   // tgt1 = tgt + SA, +ln2 stats

    // ---- long/short-term block (ln2 applied inline in qv GEMM A-staging) ----
    GEMM(0, tgt1, CD, OFF_WQV, b_qv, nullptr, qv, 512, LQ, 512, CD,
         nullptr, nullptr, ln2acc, ln2_g, ln2_b, nullptr);                   // [curr_Q|curr_V]
    cudaEventRecord(evQV, 0);
    cudaStreamWaitEvent(s2, evQV, 0);
    cudaStreamWaitEvent(s2, evB, 0);
    local_attn_tile<<<dim3(25, NH), 256, LOCAL_SMEM, s2>>>(qv, 512, qv, idkv, cat + 256, 512);
    cudaEventRecord(evL, s2);
    cudaStreamWaitEvent(0, evB, 0);
    flash_attn_tc<<<dim3(LQ / BQ, NH), 256>>>(qv, 512, qv, 512, qv + 256, 512, idkv, cat, 512);
    cudaStreamWaitEvent(0, evL, 0);
    GEMM(0, cat, 512, OFF_LTST, bltst, tgt1, tgt2, 256, LQ, CD, 512,
         nullptr, ln3acc, nullptr, nullptr, nullptr, nullptr);  // tgt2 = tgt1+LT+ST, +ln3 stats

    // ---- FFN block (ln3 applied inline in w1 GEMM A-staging) ----
    GEMM(0, tgt2, CD, OFF_W1, b1, nullptr, x1, DFF, LQ, DFF, CD,
         gnacc, nullptr, ln3acc, ln3_g, ln3_b, nullptr);                     // + fused GN stats
    dwconv_gn<<<dim3(25, 8), 256, DW_SMEM>>>(x1, gnacc, gn_g, gn_b, dw_k, x2);
    GEMM(0, x2, DFF, OFF_W2, b2, tgt2, out, 256, LQ, CD, DFF,
         nullptr, nullptr, nullptr, nullptr, nullptr, nullptr);              // out = tgt2 + FFN
}

// round 15
// speedup vs baseline: 1.0233x; 1.0233x over previous
#include <cuda_runtime.h>
#include <cuda_bf16.h>
#include <math.h>
#include <stdint.h>

#define LQ 1600
#define CD 256
#define NH 8
#define HD 32
#define DFF 1024
#define H2D 40
#define W2D 40
#define WS 15
#define WSQ 225
#define PADR 7
#define SCALE 0.17677669529663687f  // 1/sqrt(32)

#define BQ 64
#define BK 64
#define LTW 22
#define LTWW (LTW * LTW)  // 484

// GEMM chunking (BM=64, BN=64, KC=128)
#define KC 128
#define KPP 68
#define GSEG (64 * KPP)

// preconverted weight segment offsets (in bf16x2 pairs)
#define OFF_QKV  0         // [768,256] = wq | wk | wv
#define OFF_WO   98304
#define OFF_WQV  131072
#define OFF_WID  196608
#define OFF_LTST 230400
#define OFF_W1   295936
#define OFF_W2   427008
#define TOTPAIRS 558080

// ---------------- scratch (device globals; no allocation) ----------------
__device__ float g_qkv[LQ * 768];    // [q | k | v]
__device__ float g_cat[LQ * 512];
__device__ float g_tgt1[LQ * CD];
__device__ float g_qv[LQ * 512];
__device__ float g_idkv[LQ * 264];
__device__ float g_tgt2[LQ * CD];
__device__ float g_x1[LQ * DFF];
__device__ float g_x2[LQ * DFF];
__device__ float g_gnacc[64];
__device__ float g_ln1acc[LQ * 2];
__device__ float g_ln2acc[LQ * 2];
__device__ float g_ln3acc[LQ * 2];
__device__ __align__(16) uint32_t g_whi[TOTPAIRS];
__device__ __align__(16) uint32_t g_wlo[TOTPAIRS];
__device__ float g_bqkv[768];
__device__ float g_bltst[256];

// ---------------- mma helpers ----------------
__device__ __forceinline__ void mma_bf16(float* c, const uint32_t* a, const uint32_t* b) {
    asm volatile(
        "mma.sync.aligned.m16n8k16.row.col.f32.bf16.bf16.f32 "
        "{%0,%1,%2,%3}, {%4,%5,%6,%7}, {%8,%9}, {%0,%1,%2,%3};"
        : "+f"(c[0]), "+f"(c[1]), "+f"(c[2]), "+f"(c[3])
        : "r"(a[0]), "r"(a[1]), "r"(a[2]), "r"(a[3]), "r"(b[0]), "r"(b[1]));
}

__device__ __forceinline__ uint32_t pack_bf16(float lo, float hi) {
    uint32_t r;
    asm("cvt.rn.bf16x2.f32 %0, %1, %2;" : "=r"(r) : "f"(hi), "f"(lo));
    return r;
}

__device__ __forceinline__ void split_bf16_pair(float x0, float x1, uint32_t& hi, uint32_t& lo) {
    hi = pack_bf16(x0, x1);
    float h0 = __uint_as_float(hi << 16);
    float h1 = __uint_as_float(hi & 0xffff0000u);
    lo = pack_bf16(x0 - h0, x1 - h1);
}

// ---------------- per-row sum/sumsq (for fused LayerNorm) ----------------
__global__ __launch_bounds__(256) void row_stats(const float* __restrict__ in,
                                                 float* __restrict__ acc) {
    int row = blockIdx.x * 8 + (threadIdx.x >> 5);
    int lane = threadIdx.x & 31;
    const float* p = in + (size_t)row * CD + lane * 8;
    float4 a = *reinterpret_cast<const float4*>(p);
    float4 b = *reinterpret_cast<const float4*>(p + 4);
    float s = (a.x + a.y) + (a.z + a.w) + (b.x + b.y) + (b.z + b.w);
    float ss = a.x * a.x + a.y * a.y + a.z * a.z + a.w * a.w +
               b.x * b.x + b.y * b.y + b.z * b.z + b.w * b.w;
#pragma unroll
    for (int o = 16; o; o >>= 1) {
        s += __shfl_xor_sync(0xffffffffu, s, o);
        ss += __shfl_xor_sync(0xffffffffu, ss, o);
    }
    if (!lane) {
        acc[row * 2] = s;
        acc[row * 2 + 1] = ss;
    }
}

// ---------------- weight pre-conversion (once per launch) ----------------
__global__ void conv_weights(
        const float* __restrict__ wq, const float* __restrict__ wk,
        const float* __restrict__ wv, const float* __restrict__ wo,
        const float* __restrict__ wqv, const float* __restrict__ wid,
        const float* __restrict__ wlt, const float* __restrict__ wst,
        const float* __restrict__ w1, const float* __restrict__ w2,
        const float* __restrict__ bq, const float* __restrict__ bk,
        const float* __restrict__ bv, const float* __restrict__ blt,
        const float* __restrict__ bst) {
    int p = blockIdx.x * 256 + threadIdx.x;
    if (p < 256) {
        g_bqkv[p] = bq[p];
        g_bqkv[256 + p] = bk[p];
        g_bqkv[512 + p] = bv[p];
        g_bltst[p] = blt[p] + bst[p];
    }
    if (p < 64) g_gnacc[p] = 0.f;
    if (p < LQ * 2) {
        g_ln2acc[p] = 0.f;
        g_ln3acc[p] = 0.f;
    }
    if (p >= TOTPAIRS) return;
    const float* src;
    int idx;
    if (p < OFF_WO) {
        src = (p < 32768) ? wq : ((p < 65536) ? wk : wv);
        idx = (p & 32767) * 2;
    } else if (p < OFF_WQV) { src = wo; idx = (p - OFF_WO) * 2; }
    else if (p < OFF_WID) { src = wqv; idx = (p - OFF_WQV) * 2; }
    else if (p < OFF_LTST) { src = wid; idx = (p - OFF_WID) * 2; }
    else if (p < OFF_W1) {
        int lp = p - OFF_LTST;
        int n = lp >> 8, c = lp & 255;
        if (c < 128) { src = wlt; idx = (n * 128 + c) * 2; }
        else { src = wst; idx = (n * 128 + c - 128) * 2; }
    } else if (p < OFF_W2) { src = w1; idx = (p - OFF_W1) * 2; }
    else { src = w2; idx = (p - OFF_W2) * 2; }
    uint32_t hi, lo;
    split_bf16_pair(src[idx], src[idx + 1], hi, lo);
    g_whi[p] = hi;
    g_wlo[p] = lo;
}

// ---------------- bf16-split tensor-core GEMM (BM=64, BN=64) ----------------
// ldc: row stride of C. gnacc/lnacc: fused GroupNorm / per-row-LN stats of output.
// lnst+lng+lnb (+posp): LN (+pos add) applied to A rows during staging.
__global__ __launch_bounds__(256) void gemm_tc2(
        const float* __restrict__ A, int lda,
        const uint32_t* __restrict__ Whg, const uint32_t* __restrict__ Wlg,
        const float* __restrict__ bias, const float* __restrict__ res,
        float* __restrict__ C, int ldc, int M, int N, int K, float* __restrict__ gnacc,
        float* __restrict__ lnacc, const float* __restrict__ lnst,
        const float* __restrict__ lng, const float* __restrict__ lnb,
        const float* __restrict__ posp) {
    extern __shared__ uint32_t su[];
    uint32_t* Ah = su;
    uint32_t* Al = su + GSEG;
    uint32_t* Wh = su + 2 * GSEG;
    uint32_t* Wl = su + 3 * GSEG;
    __shared__ float gsum[8], gss2[8];

    int tid = threadIdx.x;
    int bm = blockIdx.y * 64, bn = blockIdx.x * 64;
    int wid = tid >> 5, lane = tid & 31;
    int wm = wid & 3, wn = wid >> 2;
    int g = lane >> 2, t = lane & 3;
    int m0 = wm * 16;
    int Kp = K >> 1;
    float acc[4][4] = {};

    int srow = tid >> 2, sc0 = tid & 3;
    bool wok = (bn + srow) < N;
    const float* Ap = A + (size_t)(bm + srow) * lda;
    const uint32_t* Whp = Whg + (size_t)(wok ? bn + srow : 0) * Kp;
    const uint32_t* Wlp = Wlg + (size_t)(wok ? bn + srow : 0) * Kp;

    float lnm = 0.f, lnr = 1.f;
    if (lnst) {
        float s = lnst[(bm + srow) * 2], ss = lnst[(bm + srow) * 2 + 1];
        lnm = s * (1.0f / CD);
        float var = ss * (1.0f / CD) - lnm * lnm;
        lnr = rsqrtf(var + 1e-5f);
    }

    float4 pa[8];
    uint4 pwh[4], pwl[4];
    const uint4 z4 = make_uint4(0, 0, 0, 0);

#define LOADCHUNK(k0)                                                          \
    {                                                                          \
        int kp0 = (k0) >> 1;                                                   \
        _Pragma("unroll")                                                      \
        for (int i = 0; i < 4; i++) {                                          \
            int cA = (k0) + (2 * sc0 + 8 * i) * 4;                             \
            pa[2 * i] = *reinterpret_cast<const float4*>(Ap + cA);             \
            pa[2 * i + 1] = *reinterpret_cast<const float4*>(Ap + cA + 4);     \
            int pp = kp0 + (sc0 + 4 * i) * 4;                                  \
            pwh[i] = wok ? *reinterpret_cast<const uint4*>(Whp + pp) : z4;     \
            pwl[i] = wok ? *reinterpret_cast<const uint4*>(Wlp + pp) : z4;     \
        }                                                                      \
    }

    LOADCHUNK(0)

    for (int k0 = 0; k0 < K; k0 += KC) {
        if (k0) __syncthreads();
#pragma unroll
        for (int i = 0; i < 4; i++) {
            float e[8] = {pa[2 * i].x, pa[2 * i].y, pa[2 * i].z, pa[2 * i].w,
                          pa[2 * i + 1].x, pa[2 * i + 1].y, pa[2 * i + 1].z, pa[2 * i + 1].w};
            if (lnst) {
                int cb = k0 + (2 * sc0 + 8 * i) * 4;
                float4 g0 = *reinterpret_cast<const float4*>(lng + cb);
                float4 g1 = *reinterpret_cast<const float4*>(lng + cb + 4);
                float4 b0 = *reinterpret_cast<const float4*>(lnb + cb);
                float4 b1 = *reinterpret_cast<const float4*>(lnb + cb + 4);
                float gv[8] = {g0.x, g0.y, g0.z, g0.w, g1.x, g1.y, g1.z, g1.w};
                float bv[8] = {b0.x, b0.y, b0.z, b0.w, b1.x, b1.y, b1.z, b1.w};
#pragma unroll
                for (int j = 0; j < 8; j++)
                    e[j] = (e[j] - lnm) * lnr * gv[j] + bv[j];
                if (posp) {
                    const float* pp2 = posp + (size_t)(bm + srow) * CD + cb;
                    float4 p0 = *reinterpret_cast<const float4*>(pp2);
                    float4 p1 = *reinterpret_cast<const float4*>(pp2 + 4);
                    e[0] += p0.x; e[1] += p0.y; e[2] += p0.z; e[3] += p0.w;
                    e[4] += p1.x; e[5] += p1.y; e[6] += p1.z; e[7] += p1.w;
                }
            }
            uint32_t h0, l0, h1, l1, h2, l2, h3, l3;
            split_bf16_pair(e[0], e[1], h0, l0);
            split_bf16_pair(e[2], e[3], h1, l1);
            split_bf16_pair(e[4], e[5], h2, l2);
            split_bf16_pair(e[6], e[7], h3, l3);
            int pp = srow * KPP + (sc0 + 4 * i) * 4;
            *reinterpret_cast<uint4*>(&Ah[pp]) = make_uint4(h0, h1, h2, h3);
            *reinterpret_cast<uint4*>(&Al[pp]) = make_uint4(l0, l1, l2, l3);
            *reinterpret_cast<uint4*>(&Wh[pp]) = pwh[i];
            *reinterpret_cast<uint4*>(&Wl[pp]) = pwl[i];
        }
        __syncthreads();
        if (k0 + KC < K) LOADCHUNK(k0 + KC)

#pragma unroll
        for (int ks = 0; ks < KC / 16; ks++) {
            int kb = ks * 8 + t;
            uint32_t ah[4], al[4];
            ah[0] = Ah[(m0 + g) * KPP + kb];
            ah[1] = Ah[(m0 + 8 + g) * KPP + kb];
            ah[2] = Ah[(m0 + g) * KPP + kb + 4];
            ah[3] = Ah[(m0 + 8 + g) * KPP + kb + 4];
            al[0] = Al[(m0 + g) * KPP + kb];
            al[1] = Al[(m0 + 8 + g) * KPP + kb];
            al[2] = Al[(m0 + g) * KPP + kb + 4];
            al[3] = Al[(m0 + 8 + g) * KPP + kb + 4];
#pragma unroll
            for (int nt = 0; nt < 4; nt++) {
                int nr = wn * 32 + nt * 8 + g;
                uint32_t bh[2] = {Wh[nr * KPP + kb], Wh[nr * KPP + kb + 4]};
                uint32_t bl[2] = {Wl[nr * KPP + kb], Wl[nr * KPP + kb + 4]};
                mma_bf16(acc[nt], ah, bh);
                mma_bf16(acc[nt], ah, bl);
                mma_bf16(acc[nt], al, bh);
            }
        }
    }

    int mo = bm + m0 + g;
    float ts = 0.f, tss = 0.f;
    float rs0 = 0.f, rq0 = 0.f, rs1 = 0.f, rq1 = 0.f;
    if (bn + 64 <= N) {
#pragma unroll
        for (int nt = 0; nt < 4; nt++) {
            int n = bn + wn * 32 + nt * 8 + 2 * t;
            float2 bv = *reinterpret_cast<const float2*>(bias + n);
            size_t o0 = (size_t)mo * ldc + n;
            size_t o1 = (size_t)(mo + 8) * ldc + n;
            float2 r0 = make_float2(acc[nt][0] + bv.x, acc[nt][1] + bv.y);
            float2 r1 = make_float2(acc[nt][2] + bv.x, acc[nt][3] + bv.y);
            if (res) {
                float2 e0 = *reinterpret_cast<const float2*>(res + o0);
                float2 e1 = *reinterpret_cast<const float2*>(res + o1);
                r0.x += e0.x; r0.y += e0.y; r1.x += e1.x; r1.y += e1.y;
            }
            if (gnacc) {
                ts += (r0.x + r0.y) + (r1.x + r1.y);
                tss += r0.x * r0.x + r0.y * r0.y + r1.x * r1.x + r1.y * r1.y;
            }
            if (lnacc) {
                rs0 += r0.x + r0.y;
                rq0 += r0.x * r0.x + r0.y * r0.y;
                rs1 += r1.x + r1.y;
                rq1 += r1.x * r1.x + r1.y * r1.y;
            }
            *reinterpret_cast<float2*>(C + o0) = r0;
            *reinterpret_cast<float2*>(C + o1) = r1;
        }
    } else {
#pragma unroll
        for (int nt = 0; nt < 4; nt++) {
            int n = bn + wn * 32 + nt * 8 + 2 * t;
#pragma unroll
            for (int e = 0; e < 2; e++) {
                if (n + e >= N) continue;
                float v0 = acc[nt][e] + bias[n + e];
                float v1 = acc[nt][2 + e] + bias[n + e];
                if (res) {
                    v0 += res[(size_t)mo * ldc + n + e];
                    v1 += res[(size_t)(mo + 8) * ldc + n + e];
                }
                C[(size_t)mo * ldc + n + e] = v0;
                C[(size_t)(mo + 8) * ldc + n + e] = v1;
            }
        }
    }
    if (lnacc) {
        rs0 += __shfl_xor_sync(0xffffffffu, rs0, 1);
        rs0 += __shfl_xor_sync(0xffffffffu, rs0, 2);
        rq0 += __shfl_xor_sync(0xffffffffu, rq0, 1);
        rq0 += __shfl_xor_sync(0xffffffffu, rq0, 2);
        rs1 += __shfl_xor_sync(0xffffffffu, rs1, 1);
        rs1 += __shfl_xor_sync(0xffffffffu, rs1, 2);
        rq1 += __shfl_xor_sync(0xffffffffu, rq1, 1);
        rq1 += __shfl_xor_sync(0xffffffffu, rq1, 2);
        if (t == 0) {
            atomicAdd(&lnacc[mo * 2], rs0);
            atomicAdd(&lnacc[mo * 2 + 1], rq0);
            atomicAdd(&lnacc[(mo + 8) * 2], rs1);
            atomicAdd(&lnacc[(mo + 8) * 2 + 1], rq1);
        }
    }
    if (gnacc) {
#pragma unroll
        for (int o = 16; o; o >>= 1) {
            ts += __shfl_xor_sync(0xffffffffu, ts, o);
            tss += __shfl_xor_sync(0xffffffffu, tss, o);
        }
        if (!lane) { gsum[wid] = ts; gss2[wid] = tss; }
        __syncthreads();
        if (tid < 2) {
            float S = gsum[tid * 4] + gsum[tid * 4 + 1] + gsum[tid * 4 + 2] + gsum[tid * 4 + 3];
            float SS = gss2[tid * 4] + gss2[tid * 4 + 1] + gss2[tid * 4 + 2] + gss2[tid * 4 + 3];
            int grp = (bn >> 5) + tid;
            atomicAdd(&gnacc[grp * 2], S);
            atomicAdd(&gnacc[grp * 2 + 1], SS);
        }
    }
#undef LOADCHUNK
}

// ---------------- tensor-core flash attention (bf16 hi/lo split) ----------------
// Per-key-half independent online softmax; exact logsumexp merge in epilogue.
__global__ __launch_bounds__(256) void flash_attn_tc(
        const float* __restrict__ Q, int ldq,
        const float* __restrict__ K, int ldk,
        const float* __restrict__ V, int ldv,
        const float* __restrict__ idkv,
        float* __restrict__ O, int ldo) {
    __shared__ uint32_t Qhi[64][20], Qlo[64][20];
    __shared__ uint32_t Khi[64][20], Klo[64][20];
    __shared__ uint32_t Vthi[32][36], Vtlo[32][36];
    __shared__ float redmax[64], redsum[64];
    __shared__ float Osm[64][33];

    int h = blockIdx.y, q0 = blockIdx.x * BQ;
    int tid = threadIdx.x, wid = tid >> 5, lane = tid & 31;
    int wm = wid & 3, wn = wid >> 2;
    int g = lane >> 2, t = lane & 3;
    int m0 = wm * 16;
    int lrow = tid >> 2, lcol = (tid & 3) * 8;

    {
        const float* qp = Q + (size_t)(q0 + lrow) * ldq + h * HD + lcol;
        float4 a = *reinterpret_cast<const float4*>(qp);
        float4 b = *reinterpret_cast<const float4*>(qp + 4);
        float xv[8] = {a.x, a.y, a.z, a.w, b.x, b.y, b.z, b.w};
#pragma unroll
        for (int j = 0; j < 4; j++) {
            uint32_t hi, lo;
            split_bf16_pair(xv[2 * j] * SCALE, xv[2 * j + 1] * SCALE, hi, lo);
            Qhi[lrow][lcol / 2 + j] = hi;
            Qlo[lrow][lcol / 2 + j] = lo;
        }
    }

    float mrow[2] = {-1e30f, -1e30f}, lsum[2] = {0.f, 0.f};
    float Oacc[4][4] = {};

    for (int kt = 0; kt < LQ; kt += BK) {
        const float* kp = K + (size_t)(kt + lrow) * ldk + h * HD + lcol;
        const float* vp = V + (size_t)(kt + lrow) * ldv + h * HD + lcol;
        float4 ka = *reinterpret_cast<const float4*>(kp);
        float4 kb = *reinterpret_cast<const float4*>(kp + 4);
        float4 va = *reinterpret_cast<const float4*>(vp);
        float4 vb = *reinterpret_cast<const float4*>(vp + 4);
        float kmul = 1.f;
        float4 ia = make_float4(0.f, 0.f, 0.f, 0.f), ib = ia;
        if (idkv) {
            const float* ip = idkv + (size_t)(kt + lrow) * 264;
            kmul = 1.f + tanhf(ip[h]);
            ia = *reinterpret_cast<const float4*>(ip + 8 + h * HD + lcol);
            ib = *reinterpret_cast<const float4*>(ip + 8 + h * HD + lcol + 4);
        }
        __syncthreads();
        {
            float kv[8] = {ka.x * kmul, ka.y * kmul, ka.z * kmul, ka.w * kmul,
                           kb.x * kmul, kb.y * kmul, kb.z * kmul, kb.w * kmul};
#pragma unroll
            for (int j = 0; j < 4; j++) {
                uint32_t hi, lo;
                split_bf16_pair(kv[2 * j], kv[2 * j + 1], hi, lo);
                Khi[lrow][lcol / 2 + j] = hi;
                Klo[lrow][lcol / 2 + j] = lo;
            }
            float vv[8] = {va.x + ia.x, va.y + ia.y, va.z + ia.z, va.w + ia.w,
                           vb.x + ib.x, vb.y + ib.y, vb.z + ib.z, vb.w + ib.w};
            __nv_bfloat16* VH = reinterpret_cast<__nv_bfloat16*>(Vthi);
            __nv_bfloat16* VL = reinterpret_cast<__nv_bfloat16*>(Vtlo);
#pragma unroll
            for (int j = 0; j < 8; j++) {
                int d = lcol + j;
                float x = vv[j];
                __nv_bfloat16 hb = __float2bfloat16(x);
                VH[d * 72 + lrow] = hb;
                VL[d * 72 + lrow] = __float2bfloat16(x - __bfloat162float(hb));
            }
        }
        __syncthreads();

        float S[4][4];
#pragma unroll
        for (int nt = 0; nt < 4; nt++)
#pragma unroll
            for (int c = 0; c < 4; c++) S[nt][c] = 0.f;
#pragma unroll
        for (int kc = 0; kc < 2; kc++) {
            uint32_t ah[4], al[4];
            ah[0] = Qhi[m0 + g][kc * 8 + t];     ah[1] = Qhi[m0 + 8 + g][kc * 8 + t];
            ah[2] = Qhi[m0 + g][kc * 8 + t + 4]; ah[3] = Qhi[m0 + 8 + g][kc * 8 + t + 4];
            al[0] = Qlo[m0 + g][kc * 8 + t];     al[1] = Qlo[m0 + 8 + g][kc * 8 + t];
            al[2] = Qlo[m0 + g][kc * 8 + t + 4]; al[3] = Qlo[m0 + 8 + g][kc * 8 + t + 4];
#pragma unroll
            for (int nt = 0; nt < 4; nt++) {
                int kr = wn * 32 + nt * 8 + g;
                uint32_t bh[2] = {Khi[kr][kc * 8 + t], Khi[kr][kc * 8 + t + 4]};
                uint32_t bl[2] = {Klo[kr][kc * 8 + t], Klo[kr][kc * 8 + t + 4]};
                mma_bf16(S[nt], ah, bh);
                mma_bf16(S[nt], ah, bl);
                mma_bf16(S[nt], al, bh);
            }
        }

        float pmA = -1e30f, pmB = -1e30f;
#pragma unroll
        for (int nt = 0; nt < 4; nt++) {
            pmA = fmaxf(pmA, fmaxf(S[nt][0], S[nt][1]));
            pmB = fmaxf(pmB, fmaxf(S[nt][2], S[nt][3]));
        }
        pmA = fmaxf(pmA, __shfl_xor_sync(0xffffffffu, pmA, 1));
        pmA = fmaxf(pmA, __shfl_xor_sync(0xffffffffu, pmA, 2));
        pmB = fmaxf(pmB, __shfl_xor_sync(0xffffffffu, pmB, 1));
        pmB = fmaxf(pmB, __shfl_xor_sync(0xffffffffu, pmB, 2));
        float nmA = fmaxf(mrow[0], pmA);
        float nmB = fmaxf(mrow[1], pmB);
        float alA = __expf(mrow[0] - nmA), alB = __expf(mrow[1] - nmB);
        mrow[0] = nmA; mrow[1] = nmB;
        float psA = 0.f, psB = 0.f;
#pragma unroll
        for (int nt = 0; nt < 4; nt++) {
            S[nt][0] = __expf(S[nt][0] - nmA); S[nt][1] = __expf(S[nt][1] - nmA);
            S[nt][2] = __expf(S[nt][2] - nmB); S[nt][3] = __expf(S[nt][3] - nmB);
            psA += S[nt][0] + S[nt][1];
            psB += S[nt][2] + S[nt][3];
        }
        psA += __shfl_xor_sync(0xffffffffu, psA, 1);
        psA += __shfl_xor_sync(0xffffffffu, psA, 2);
        psB += __shfl_xor_sync(0xffffffffu, psB, 1);
        psB += __shfl_xor_sync(0xffffffffu, psB, 2);
        lsum[0] = lsum[0] * alA + psA;
        lsum[1] = lsum[1] * alB + psB;
#pragma unroll
        for (int nt = 0; nt < 4; nt++) {
            Oacc[nt][0] *= alA; Oacc[nt][1] *= alA;
            Oacc[nt][2] *= alB; Oacc[nt][3] *= alB;
        }

#pragma unroll
        for (int kc2 = 0; kc2 < 2; kc2++) {
            uint32_t ph[4], pl[4];
            split_bf16_pair(S[2 * kc2][0], S[2 * kc2][1], ph[0], pl[0]);
            split_bf16_pair(S[2 * kc2][2], S[2 * kc2][3], ph[1], pl[1]);
            split_bf16_pair(S[2 * kc2 + 1][0], S[2 * kc2 + 1][1], ph[2], pl[2]);
            split_bf16_pair(S[2 * kc2 + 1][2], S[2 * kc2 + 1][3], ph[3], pl[3]);
            int cb = wn * 16 + kc2 * 8 + t;
#pragma unroll
            for (int ntv = 0; ntv < 4; ntv++) {
                int vr = ntv * 8 + g;
                uint32_t bh[2] = {Vthi[vr][cb], Vthi[vr][cb + 4]};
                uint32_t bl[2] = {Vtlo[vr][cb], Vtlo[vr][cb + 4]};
                mma_bf16(Oacc[ntv], ph, bh);
                mma_bf16(Oacc[ntv], ph, bl);
                mma_bf16(Oacc[ntv], pl, bh);
            }
        }
    }

    if (wn == 0) {
#pragma unroll
        for (int ntv = 0; ntv < 4; ntv++) {
            int d = ntv * 8 + 2 * t;
            Osm[m0 + g][d] = Oacc[ntv][0];
            Osm[m0 + g][d + 1] = Oacc[ntv][1];
            Osm[m0 + 8 + g][d] = Oacc[ntv][2];
            Osm[m0 + 8 + g][d + 1] = Oacc[ntv][3];
        }
        if (t == 0) {
            redmax[m0 + g] = mrow[0];
            redsum[m0 + g] = lsum[0];
            redmax[m0 + 8 + g] = mrow[1];
            redsum[m0 + 8 + g] = lsum[1];
        }
    }
    __syncthreads();
    if (wn == 1) {
        float mA0 = redmax[m0 + g], lA0 = redsum[m0 + g];
        float mB0 = redmax[m0 + 8 + g], lB0 = redsum[m0 + 8 + g];
        float MA = fmaxf(mA0, mrow[0]), MB = fmaxf(mB0, mrow[1]);
        float eA0 = __expf(mA0 - MA), eA1 = __expf(mrow[0] - MA);
        float eB0 = __expf(mB0 - MB), eB1 = __expf(mrow[1] - MB);
        float invA = 1.0f / (lA0 * eA0 + lsum[0] * eA1);
        float invB = 1.0f / (lB0 * eB0 + lsum[1] * eB1);
#pragma unroll
        for (int ntv = 0; ntv < 4; ntv++) {
            int d = ntv * 8 + 2 * t;
            float* op0 = O + (size_t)(q0 + m0 + g) * ldo + h * HD + d;
            float* op1 = O + (size_t)(q0 + m0 + 8 + g) * ldo + h * HD + d;
            op0[0] = (Osm[m0 + g][d] * eA0 + Oacc[ntv][0] * eA1) * invA;
            op0[1] = (Osm[m0 + g][d + 1] * eA0 + Oacc[ntv][1] * eA1) * invA;
            op1[0] = (Osm[m0 + 8 + g][d] * eB0 + Oacc[ntv][2] * eB1) * invB;
            op1[1] = (Osm[m0 + 8 + g][d + 1] * eB0 + Oacc[ntv][3] * eB1) * invB;
        }
    }
}

// ---------------- tiled local attention with fused global-KV transform ----------------
__global__ __launch_bounds__(256) void local_attn_tile(
        const float* __restrict__ Q, int ldq,
        const float* __restrict__ qvbuf, const float* __restrict__ idkv,
        float* __restrict__ O, int ldo) {
    extern __shared__ float sm[];
    float* winK = sm;
    float* winV = sm + LTWW * 33;
    float* pb = sm + 2 * LTWW * 33;
    int h = blockIdx.y;
    int ty0 = (blockIdx.x / 5) * 8, tx0 = (blockIdx.x % 5) * 8;
    int wy0 = ty0 - PADR, wx0 = tx0 - PADR;
    int tid = threadIdx.x, w = tid >> 5, lane = tid & 31;

    for (int idx = tid; idx < LTWW * 32; idx += 256) {
        int pos = idx >> 5, d = idx & 31;
        int gy = wy0 + pos / LTW, gx = wx0 + pos % LTW;
        bool ok = ((unsigned)gy < H2D) && ((unsigned)gx < W2D);
        float kvv = 0.f, vvv = 0.f;
        if (ok) {
            size_t r = (size_t)(gy * W2D + gx);
            float ik = idkv[r * 264 + h];
            kvv = qvbuf[r * 512 + h * HD + d] * (1.0f + tanhf(ik));
            vvv = qvbuf[r * 512 + 256 + h * HD + d] + idkv[r * 264 + 8 + h * HD + d];
        }
        winK[pos * 33 + d] = kvv;
        winV[pos * 33 + d] = vvv;
    }
    __syncthreads();

    int qy = ty0 + w;
    for (int qi = 0; qi < 8; qi++) {
        int qx = tx0 + qi;
        float qv = Q[(size_t)(qy * W2D + qx) * ldq + h * HD + lane] * SCALE;
        float lg[8];
        int wi[8];
        bool val[8];
#pragma unroll
        for (int c = 0; c < 8; c++) {
            int j = c * 32 + lane;
            int jr = j / 15, jc = j - jr * 15;
            int gy2 = qy + jr - PADR, gx2 = qx + jc - PADR;
            val[c] = (j < WSQ) && ((unsigned)gy2 < H2D) && ((unsigned)gx2 < W2D);
            wi[c] = (j < WSQ) ? ((w + jr) * LTW + (qi + jc)) : 0;
            lg[c] = 0.f;
        }
#pragma unroll 8
        for (int d = 0; d < 32; d++) {
            float qd = __shfl_sync(0xffffffffu, qv, d);
#pragma unroll
            for (int c = 0; c < 8; c++)
                lg[c] = fmaf(qd, winK[wi[c] * 33 + d], lg[c]);
        }
        float mx = -1e30f;
#pragma unroll
        for (int c = 0; c < 8; c++) {
            lg[c] = val[c] ? lg[c] : -1e30f;
            mx = fmaxf(mx, lg[c]);
        }
#pragma unroll
        for (int o = 16; o; o >>= 1) mx = fmaxf(mx, __shfl_xor_sync(0xffffffffu, mx, o));
        float s = 0.f;
#pragma unroll
        for (int c = 0; c < 8; c++) {
            lg[c] = __expf(lg[c] - mx);
            s += lg[c];
        }
#pragma unroll
        for (int o = 16; o; o >>= 1) s += __shfl_xor_sync(0xffffffffu, s, o);
        float inv = 1.0f / s;
#pragma unroll
        for (int c = 0; c < 8; c++) pb[w * 264 + c * 32 + lane] = lg[c] * inv;
        __syncwarp();

        float oacc = 0.f;
        int j = 0;
#pragma unroll
        for (int jr = 0; jr < 15; jr++) {
            int base = ((w + jr) * LTW + qi) * 33 + lane;
#pragma unroll
            for (int jc = 0; jc < 15; jc++) {
                oacc = fmaf(pb[w * 264 + j], winV[base + jc * 33], oacc);
                j++;
            }
        }
        O[(size_t)(qy * W2D + qx) * ldo + h * HD + lane] = oacc;
        __syncwarp();
    }
}

// ---------------- fused GN-apply + GELU + depthwise 5x5 conv ----------------
#define DWP 144
__global__ __launch_bounds__(256) void dwconv_gn(
        const float* __restrict__ x1, const float* __restrict__ acc,
        const float* __restrict__ gg, const float* __restrict__ gb,
        const float* __restrict__ dwk, float* __restrict__ y) {
    extern __shared__ float sm[];
    float* winX = sm;
    float* wk = sm + DWP * 128;
    float* sgg = wk + 128 * 25;
    float* sgb = sgg + 128;
    float* smr = sgb + 128;
    int tile = blockIdx.x, slab = blockIdx.y;
    int ty0 = (tile / 5) * 8, tx0 = (tile % 5) * 8;
    int tid = threadIdx.x;
    int c0 = slab * 128;

    if (tid < 4) {
        int gidx = (c0 >> 5) + tid;
        const float inv = 1.0f / 51200.0f;
        float s = acc[gidx * 2], ss = acc[gidx * 2 + 1];
        float m = s * inv;
        float var = ss * inv - m * m;
        smr[tid] = m;
        smr[4 + tid] = rsqrtf(var + 1e-5f);
    }
    if (tid < 128) {
        sgg[tid] = gg[c0 + tid];
        sgb[tid] = gb[c0 + tid];
    }
    for (int i = tid; i < 128 * 25; i += 256) wk[i] = dwk[c0 * 25 + i];
    __syncthreads();

    for (int idx = tid; idx < DWP * 32; idx += 256) {
        int pos = idx >> 5, f4 = idx & 31;
        int gy = ty0 - 2 + pos / 12, gx = tx0 - 2 + pos % 12;
        bool ok = ((unsigned)gy < H2D) && ((unsigned)gx < W2D);
        float4 v = ok ? *reinterpret_cast<const float4*>(
                            x1 + (size_t)(gy * W2D + gx) * DFF + c0 + f4 * 4)
                      : make_float4(0.f, 0.f, 0.f, 0.f);
        int grp = f4 >> 3;
        float m = smr[grp], r = smr[4 + grp];
        int cl = f4 * 4;
        float e[4] = {v.x, v.y, v.z, v.w};
#pragma unroll
        for (int j = 0; j < 4; j++) {
            float t2 = (e[j] - m) * r * sgg[cl + j] + sgb[cl + j];
            e[j] = 0.5f * t2 * (1.0f + erff(t2 * 0.70710678118654752f));
        }
        float4 o = make_float4(ok ? e[0] : 0.f, ok ? e[1] : 0.f,
                               ok ? e[2] : 0.f, ok ? e[3] : 0.f);
        *reinterpret_cast<float4*>(&winX[pos * 128 + cl]) = o;
    }
    __syncthreads();

    int c = tid & 127, pg = tid >> 7;
    float wreg[25];
#pragma unroll
    for (int k = 0; k < 25; k++) wreg[k] = wk[c * 25 + k];

#pragma unroll
    for (int py = 0; py < 4; py++) {
        int oy = pg * 4 + py;
        float oac[8] = {};
#pragma unroll
        for (int dy = 0; dy < 5; dy++) {
            float rv[12];
            int rb = (oy + dy) * 12;
#pragma unroll
            for (int j = 0; j < 12; j++) rv[j] = winX[(rb + j) * 128 + c];
#pragma unroll
            for (int dx = 0; dx < 5; dx++) {
                float wv = wreg[dy * 5 + dx];
#pragma unroll
                for (int o = 0; o < 8; o++)
                    oac[o] = fmaf(rv[o + dx], wv, oac[o]);
            }
        }
#pragma unroll
        for (int o = 0; o < 8; o++)
            y[(size_t)((ty0 + oy) * W2D + tx0 + o) * DFF + c0 + c] = oac[o];
    }
}

// ---------------- host ----------------
static const int GEMM_SMEM = 4 * GSEG * (int)sizeof(uint32_t);
static const int DW_SMEM = (DWP * 128 + 128 * 25 + 256 + 8) * (int)sizeof(float);

extern "C" void kernel_launch(void* const* d_in, const int* in_sizes, int n_in,
                              void* d_out, int out_size) {
    const float* tgt = (const float*)d_in[0];
    const float* curr_id_emb = (const float*)d_in[1];
    const float* self_pos = (const float*)d_in[2];
    const float* ln1_g = (const float*)d_in[3];
    const float* ln1_b = (const float*)d_in[4];
    const float* sa_wq = (const float*)d_in[5];
    const float* sa_bq = (const float*)d_in[6];
    const float* sa_wk = (const float*)d_in[7];
    const float* sa_bk = (const float*)d_in[8];
    const float* sa_wv = (const float*)d_in[9];
    const float* sa_bv = (const float*)d_in[10];
    const float* sa_wo = (const float*)d_in[11];
    const float* sa_bo = (const float*)d_in[12];
    const float* ln2_g = (const float*)d_in[13];
    const float* ln2_b = (const float*)d_in[14];
    const float* w_qv = (const float*)d_in[15];
    const float* b_qv = (const float*)d_in[16];
    const float* w_id = (const float*)d_in[17];
    const float* b_id = (const float*)d_in[18];
    const float* lt_wo = (const float*)d_in[19];
    const float* lt_bo = (const float*)d_in[20];
    const float* st_wo = (const float*)d_in[21];
    const float* st_bo = (const float*)d_in[22];
    const float* ln3_g = (const float*)d_in[23];
    const float* ln3_b = (const float*)d_in[24];
    const float* w1 = (const float*)d_in[25];
    const float* b1 = (const float*)d_in[26];
    const float* gn_g = (const float*)d_in[27];
    const float* gn_b = (const float*)d_in[28];
    const float* dw_k = (const float*)d_in[29];
    const float* w2 = (const float*)d_in[30];
    const float* b2 = (const float*)d_in[31];
    float* out = (float*)d_out;

    float *qkv, *cat, *tgt1, *qv, *idkv, *tgt2, *x1, *x2, *gnacc;
    float *ln1acc, *ln2acc, *ln3acc, *bqkv, *bltst;
    uint32_t *whi, *wlo;
    cudaGetSymbolAddress((void**)&qkv, g_qkv);
    cudaGetSymbolAddress((void**)&cat, g_cat);
    cudaGetSymbolAddress((void**)&tgt1, g_tgt1);
    cudaGetSymbolAddress((void**)&qv, g_qv);
    cudaGetSymbolAddress((void**)&idkv, g_idkv);
    cudaGetSymbolAddress((void**)&tgt2, g_tgt2);
    cudaGetSymbolAddress((void**)&x1, g_x1);
    cudaGetSymbolAddress((void**)&x2, g_x2);
    cudaGetSymbolAddress((void**)&gnacc, g_gnacc);
    cudaGetSymbolAddress((void**)&ln1acc, g_ln1acc);
    cudaGetSymbolAddress((void**)&ln2acc, g_ln2acc);
    cudaGetSymbolAddress((void**)&ln3acc, g_ln3acc);
    cudaGetSymbolAddress((void**)&bqkv, g_bqkv);
    cudaGetSymbolAddress((void**)&bltst, g_bltst);
    cudaGetSymbolAddress((void**)&whi, g_whi);
    cudaGetSymbolAddress((void**)&wlo, g_wlo);

    const int LOCAL_SMEM = (2 * LTWW * 33 + 8 * 264) * (int)sizeof(float);

    static bool init = false;
    static cudaStream_t s1, s2;
    static cudaEvent_t evR, evW, evB, evL1, evV, evQV, evL;
    if (!init) {
        cudaStreamCreateWithFlags(&s1, cudaStreamNonBlocking);
        cudaStreamCreateWithFlags(&s2, cudaStreamNonBlocking);
        cudaEventCreateWithFlags(&evR, cudaEventDisableTiming);
        cudaEventCreateWithFlags(&evW, cudaEventDisableTiming);
        cudaEventCreateWithFlags(&evB, cudaEventDisableTiming);
        cudaEventCreateWithFlags(&evL1, cudaEventDisableTiming);
        cudaEventCreateWithFlags(&evV, cudaEventDisableTiming);
        cudaEventCreateWithFlags(&evQV, cudaEventDisableTiming);
        cudaEventCreateWithFlags(&evL, cudaEventDisableTiming);
        cudaFuncSetAttribute(local_attn_tile, cudaFuncAttributeMaxDynamicSharedMemorySize, LOCAL_SMEM);
        cudaFuncSetAttribute(gemm_tc2, cudaFuncAttributeMaxDynamicSharedMemorySize, GEMM_SMEM);
        cudaFuncSetAttribute(dwconv_gn, cudaFuncAttributeMaxDynamicSharedMemorySize, DW_SMEM);
        init = true;
    }

    auto GEMM = [&](cudaStream_t st, const float* A, int lda, int woff, const float* bias,
                    const float* res, float* C, int ldc, int M, int N, int K, float* gn,
                    float* lnacc, const float* lnst, const float* lng, const float* lnb,
                    const float* posp) {
        dim3 grid((N + 63) / 64, (M + 63) / 64);
        gemm_tc2<<<grid, 256, GEMM_SMEM, st>>>(A, lda, whi + woff, wlo + woff, bias, res, C,
                                               ldc, M, N, K, gn, lnacc, lnst, lng, lnb, posp);
    };

    // ---- fork: side stream does weight conversion + idkv GEMM ----
    cudaEventRecord(evR, 0);
    cudaStreamWaitEvent(s1, evR, 0);
    conv_weights<<<(TOTPAIRS + 255) / 256, 256, 0, s1>>>(
        sa_wq, sa_wk, sa_wv, sa_wo, w_qv, w_id, lt_wo, st_wo, w1, w2,
        sa_bq, sa_bk, sa_bv, lt_bo, st_bo);
    cudaEventRecord(evW, s1);
    GEMM(s1, curr_id_emb, CD, OFF_WID, b_id, nullptr, idkv, 264, LQ, 264, CD,
         nullptr, nullptr, nullptr, nullptr, nullptr, nullptr);
    cudaEventRecord(evB, s1);

    // ---- self-attention block: qk GEMM (stream 0) || v GEMM (s2), packed qkv ----
    row_stats<<<LQ / 8, 256>>>(tgt, ln1acc);
    cudaEventRecord(evL1, 0);
    cudaStreamWaitEvent(0, evW, 0);
    GEMM(0, tgt, CD, OFF_QKV, bqkv, nullptr, qkv, 768, LQ, 512, CD,
         nullptr, nullptr, ln1acc, ln1_g, ln1_b, self_pos);                  // [q|k]
    cudaStreamWaitEvent(s2, evW, 0);
    cudaStreamWaitEvent(s2, evL1, 0);
    GEMM(s2, tgt, CD, OFF_QKV + 65536, bqkv + 512, nullptr, qkv + 512, 768, LQ, CD, CD,
         nullptr, nullptr, ln1acc, ln1_g, ln1_b, nullptr);                   // v (parallel)
    cudaEventRecord(evV, s2);
    cudaStreamWaitEvent(0, evV, 0);
    flash_attn_tc<<<dim3(LQ / BQ, NH), 256>>>(qkv, 768, qkv + 256, 768, qkv + 512, 768,
                                              nullptr, cat, 512);
    GEMM(0, cat, 512, OFF_WO, sa_bo, tgt, tgt1, 256, LQ, CD, CD,
         nullptr, ln2acc, nullptr, nullptr, nullptr, nullptr);   // tgt1 = tgt + SA, +ln2 stats

    // ---- long/short-term block (ln2 applied inline in qv GEMM A-staging) ----
    GEMM(0, tgt1, CD, OFF_WQV, b_qv, nullptr, qv, 512, LQ, 512, CD,
         nullptr, nullptr, ln2acc, ln2_g, ln2_b, nullptr);                   // [curr_Q|curr_V]
    cudaEventRecord(evQV, 0);
    cudaStreamWaitEvent(s2, evQV, 0);
    cudaStreamWaitEvent(s2, evB, 0);
    local_attn_tile<<<dim3(25, NH), 256, LOCAL_SMEM, s2>>>(qv, 512, qv, idkv, cat + 256, 512);
    cudaEventRecord(evL, s2);
    cudaStreamWaitEvent(0, evB, 0);
    flash_attn_tc<<<dim3(LQ / BQ, NH), 256>>>(qv, 512, qv, 512, qv + 256, 512, idkv, cat, 512);
    cudaStreamWaitEvent(0, evL, 0);
    GEMM(0, cat, 512, OFF_LTST, bltst, tgt1, tgt2, 256, LQ, CD, 512,
         nullptr, ln3acc, nullptr, nullptr, nullptr, nullptr);  // tgt2 = tgt1+LT+ST, +ln3 stats

    // ---- FFN block (ln3 applied inline in w1 GEMM A-staging) ----
    GEMM(0, tgt2, CD, OFF_W1, b1, nullptr, x1, DFF, LQ, DFF, CD,
         gnacc, nullptr, ln3acc, ln3_g, ln3_b, nullptr);                     // + fused GN stats
    dwconv_gn<<<dim3(25, 8), 256, DW_SMEM>>>(x1, gnacc, gn_g, gn_b, dw_k, x2);
    GEMM(0, x2, DFF, OFF_W2, b2, tgt2, out, 256, LQ, CD, DFF,
         nullptr, nullptr, nullptr, nullptr, nullptr, nullptr);              // out = tgt2 + FFN
}

// round 16
// speedup vs baseline: 1.0509x; 1.0269x over previous
#include <cuda_runtime.h>
#include <cuda_bf16.h>
#include <math.h>
#include <stdint.h>

#define LQ 1600
#define CD 256
#define NH 8
#define HD 32
#define DFF 1024
#define H2D 40
#define W2D 40
#define WS 15
#define WSQ 225
#define PADR 7
#define SCALE 0.17677669529663687f  // 1/sqrt(32)

#define BQ 64
#define BK 64
#define LTW 22
#define LTWW (LTW * LTW)  // 484

// GEMM chunking (BM=64, BN=64, KC=128)
#define KC 128
#define KPP 68
#define GSEG (64 * KPP)

// preconverted weight segment offsets (in bf16x2 pairs)
#define OFF_QKV  0         // [768,256] = wq | wk | wv
#define OFF_WO   98304
#define OFF_WQV  131072
#define OFF_WID  196608
#define OFF_LTST 230400
#define OFF_W1   295936
#define OFF_W2   427008
#define TOTPAIRS 558080

// flash dynamic smem layout (uint32 words)
#define FA_Q    0                    // Qhi[64*20], Qlo[64*20]
#define FA_K    (FA_Q + 2560)        // Khi[2][64*20], Klo[2][64*20]
#define FA_V    (FA_K + 5120)        // Vthi[2][32*36], Vtlo[2][32*36]
#define FA_RED  (FA_V + 4608)        // redmax[64], redsum[64]
#define FA_OSM  (FA_RED + 128)       // Osm[64*33]
#define FA_TOT  (FA_OSM + 2112)      // 14528 words = 58112 B

// ---------------- scratch (device globals; no allocation) ----------------
__device__ float g_qkv[LQ * 768];    // [q | k | v]
__device__ float g_cat[LQ * 512];
__device__ float g_tgt1[LQ * CD];
__device__ float g_qv[LQ * 512];
__device__ float g_idkv[LQ * 264];
__device__ float g_tgt2[LQ * CD];
__device__ float g_x1[LQ * DFF];
__device__ float g_x2[LQ * DFF];
__device__ float g_gnacc[64];
__device__ float g_ln1acc[LQ * 2];
__device__ float g_ln2acc[LQ * 2];
__device__ float g_ln3acc[LQ * 2];
__device__ __align__(16) uint32_t g_whi[TOTPAIRS];
__device__ __align__(16) uint32_t g_wlo[TOTPAIRS];
__device__ float g_bqkv[768];
__device__ float g_bltst[256];

// ---------------- mma helpers ----------------
__device__ __forceinline__ void mma_bf16(float* c, const uint32_t* a, const uint32_t* b) {
    asm volatile(
        "mma.sync.aligned.m16n8k16.row.col.f32.bf16.bf16.f32 "
        "{%0,%1,%2,%3}, {%4,%5,%6,%7}, {%8,%9}, {%0,%1,%2,%3};"
        : "+f"(c[0]), "+f"(c[1]), "+f"(c[2]), "+f"(c[3])
        : "r"(a[0]), "r"(a[1]), "r"(a[2]), "r"(a[3]), "r"(b[0]), "r"(b[1]));
}

__device__ __forceinline__ uint32_t pack_bf16(float lo, float hi) {
    uint32_t r;
    asm("cvt.rn.bf16x2.f32 %0, %1, %2;" : "=r"(r) : "f"(hi), "f"(lo));
    return r;
}

__device__ __forceinline__ void split_bf16_pair(float x0, float x1, uint32_t& hi, uint32_t& lo) {
    hi = pack_bf16(x0, x1);
    float h0 = __uint_as_float(hi << 16);
    float h1 = __uint_as_float(hi & 0xffff0000u);
    lo = pack_bf16(x0 - h0, x1 - h1);
}

// ---------------- per-row sum/sumsq (for fused LayerNorm) ----------------
__global__ __launch_bounds__(256) void row_stats(const float* __restrict__ in,
                                                 float* __restrict__ acc) {
    int row = blockIdx.x * 8 + (threadIdx.x >> 5);
    int lane = threadIdx.x & 31;
    const float* p = in + (size_t)row * CD + lane * 8;
    float4 a = *reinterpret_cast<const float4*>(p);
    float4 b = *reinterpret_cast<const float4*>(p + 4);
    float s = (a.x + a.y) + (a.z + a.w) + (b.x + b.y) + (b.z + b.w);
    float ss = a.x * a.x + a.y * a.y + a.z * a.z + a.w * a.w +
               b.x * b.x + b.y * b.y + b.z * b.z + b.w * b.w;
#pragma unroll
    for (int o = 16; o; o >>= 1) {
        s += __shfl_xor_sync(0xffffffffu, s, o);
        ss += __shfl_xor_sync(0xffffffffu, ss, o);
    }
    if (!lane) {
        acc[row * 2] = s;
        acc[row * 2 + 1] = ss;
    }
}

// ---------------- weight pre-conversion (once per launch) ----------------
__global__ void conv_weights(
        const float* __restrict__ wq, const float* __restrict__ wk,
        const float* __restrict__ wv, const float* __restrict__ wo,
        const float* __restrict__ wqv, const float* __restrict__ wid,
        const float* __restrict__ wlt, const float* __restrict__ wst,
        const float* __restrict__ w1, const float* __restrict__ w2,
        const float* __restrict__ bq, const float* __restrict__ bk,
        const float* __restrict__ bv, const float* __restrict__ blt,
        const float* __restrict__ bst) {
    int p = blockIdx.x * 256 + threadIdx.x;
    if (p < 256) {
        g_bqkv[p] = bq[p];
        g_bqkv[256 + p] = bk[p];
        g_bqkv[512 + p] = bv[p];
        g_bltst[p] = blt[p] + bst[p];
    }
    if (p < 64) g_gnacc[p] = 0.f;
    if (p < LQ * 2) {
        g_ln2acc[p] = 0.f;
        g_ln3acc[p] = 0.f;
    }
    if (p >= TOTPAIRS) return;
    const float* src;
    int idx;
    if (p < OFF_WO) {
        src = (p < 32768) ? wq : ((p < 65536) ? wk : wv);
        idx = (p & 32767) * 2;
    } else if (p < OFF_WQV) { src = wo; idx = (p - OFF_WO) * 2; }
    else if (p < OFF_WID) { src = wqv; idx = (p - OFF_WQV) * 2; }
    else if (p < OFF_LTST) { src = wid; idx = (p - OFF_WID) * 2; }
    else if (p < OFF_W1) {
        int lp = p - OFF_LTST;
        int n = lp >> 8, c = lp & 255;
        if (c < 128) { src = wlt; idx = (n * 128 + c) * 2; }
        else { src = wst; idx = (n * 128 + c - 128) * 2; }
    } else if (p < OFF_W2) { src = w1; idx = (p - OFF_W1) * 2; }
    else { src = w2; idx = (p - OFF_W2) * 2; }
    uint32_t hi, lo;
    split_bf16_pair(src[idx], src[idx + 1], hi, lo);
    g_whi[p] = hi;
    g_wlo[p] = lo;
}

// ---------------- bf16-split tensor-core GEMM (BM=64, BN=64) ----------------
__global__ __launch_bounds__(256) void gemm_tc2(
        const float* __restrict__ A, int lda,
        const uint32_t* __restrict__ Whg, const uint32_t* __restrict__ Wlg,
        const float* __restrict__ bias, const float* __restrict__ res,
        float* __restrict__ C, int ldc, int M, int N, int K, float* __restrict__ gnacc,
        float* __restrict__ lnacc, const float* __restrict__ lnst,
        const float* __restrict__ lng, const float* __restrict__ lnb,
        const float* __restrict__ posp) {
    extern __shared__ uint32_t su[];
    uint32_t* Ah = su;
    uint32_t* Al = su + GSEG;
    uint32_t* Wh = su + 2 * GSEG;
    uint32_t* Wl = su + 3 * GSEG;
    __shared__ float gsum[8], gss2[8];

    int tid = threadIdx.x;
    int bm = blockIdx.y * 64, bn = blockIdx.x * 64;
    int wid = tid >> 5, lane = tid & 31;
    int wm = wid & 3, wn = wid >> 2;
    int g = lane >> 2, t = lane & 3;
    int m0 = wm * 16;
    int Kp = K >> 1;
    float acc[4][4] = {};

    int srow = tid >> 2, sc0 = tid & 3;
    bool wok = (bn + srow) < N;
    const float* Ap = A + (size_t)(bm + srow) * lda;
    const uint32_t* Whp = Whg + (size_t)(wok ? bn + srow : 0) * Kp;
    const uint32_t* Wlp = Wlg + (size_t)(wok ? bn + srow : 0) * Kp;

    float lnm = 0.f, lnr = 1.f;
    if (lnst) {
        float s = lnst[(bm + srow) * 2], ss = lnst[(bm + srow) * 2 + 1];
        lnm = s * (1.0f / CD);
        float var = ss * (1.0f / CD) - lnm * lnm;
        lnr = rsqrtf(var + 1e-5f);
    }

    float4 pa[8];
    uint4 pwh[4], pwl[4];
    const uint4 z4 = make_uint4(0, 0, 0, 0);

#define LOADCHUNK(k0)                                                          \
    {                                                                          \
        int kp0 = (k0) >> 1;                                                   \
        _Pragma("unroll")                                                      \
        for (int i = 0; i < 4; i++) {                                          \
            int cA = (k0) + (2 * sc0 + 8 * i) * 4;                             \
            pa[2 * i] = *reinterpret_cast<const float4*>(Ap + cA);             \
            pa[2 * i + 1] = *reinterpret_cast<const float4*>(Ap + cA + 4);     \
            int pp = kp0 + (sc0 + 4 * i) * 4;                                  \
            pwh[i] = wok ? *reinterpret_cast<const uint4*>(Whp + pp) : z4;     \
            pwl[i] = wok ? *reinterpret_cast<const uint4*>(Wlp + pp) : z4;     \
        }                                                                      \
    }

    LOADCHUNK(0)

    for (int k0 = 0; k0 < K; k0 += KC) {
        if (k0) __syncthreads();
#pragma unroll
        for (int i = 0; i < 4; i++) {
            float e[8] = {pa[2 * i].x, pa[2 * i].y, pa[2 * i].z, pa[2 * i].w,
                          pa[2 * i + 1].x, pa[2 * i + 1].y, pa[2 * i + 1].z, pa[2 * i + 1].w};
            if (lnst) {
                int cb = k0 + (2 * sc0 + 8 * i) * 4;
                float4 g0 = *reinterpret_cast<const float4*>(lng + cb);
                float4 g1 = *reinterpret_cast<const float4*>(lng + cb + 4);
                float4 b0 = *reinterpret_cast<const float4*>(lnb + cb);
                float4 b1 = *reinterpret_cast<const float4*>(lnb + cb + 4);
                float gv[8] = {g0.x, g0.y, g0.z, g0.w, g1.x, g1.y, g1.z, g1.w};
                float bv[8] = {b0.x, b0.y, b0.z, b0.w, b1.x, b1.y, b1.z, b1.w};
#pragma unroll
                for (int j = 0; j < 8; j++)
                    e[j] = (e[j] - lnm) * lnr * gv[j] + bv[j];
                if (posp) {
                    const float* pp2 = posp + (size_t)(bm + srow) * CD + cb;
                    float4 p0 = *reinterpret_cast<const float4*>(pp2);
                    float4 p1 = *reinterpret_cast<const float4*>(pp2 + 4);
                    e[0] += p0.x; e[1] += p0.y; e[2] += p0.z; e[3] += p0.w;
                    e[4] += p1.x; e[5] += p1.y; e[6] += p1.z; e[7] += p1.w;
                }
            }
            uint32_t h0, l0, h1, l1, h2, l2, h3, l3;
            split_bf16_pair(e[0], e[1], h0, l0);
            split_bf16_pair(e[2], e[3], h1, l1);
            split_bf16_pair(e[4], e[5], h2, l2);
            split_bf16_pair(e[6], e[7], h3, l3);
            int pp = srow * KPP + (sc0 + 4 * i) * 4;
            *reinterpret_cast<uint4*>(&Ah[pp]) = make_uint4(h0, h1, h2, h3);
            *reinterpret_cast<uint4*>(&Al[pp]) = make_uint4(l0, l1, l2, l3);
            *reinterpret_cast<uint4*>(&Wh[pp]) = pwh[i];
            *reinterpret_cast<uint4*>(&Wl[pp]) = pwl[i];
        }
        __syncthreads();
        if (k0 + KC < K) LOADCHUNK(k0 + KC)

#pragma unroll
        for (int ks = 0; ks < KC / 16; ks++) {
            int kb = ks * 8 + t;
            uint32_t ah[4], al[4];
            ah[0] = Ah[(m0 + g) * KPP + kb];
            ah[1] = Ah[(m0 + 8 + g) * KPP + kb];
            ah[2] = Ah[(m0 + g) * KPP + kb + 4];
            ah[3] = Ah[(m0 + 8 + g) * KPP + kb + 4];
            al[0] = Al[(m0 + g) * KPP + kb];
            al[1] = Al[(m0 + 8 + g) * KPP + kb];
            al[2] = Al[(m0 + g) * KPP + kb + 4];
            al[3] = Al[(m0 + 8 + g) * KPP + kb + 4];
#pragma unroll
            for (int nt = 0; nt < 4; nt++) {
                int nr = wn * 32 + nt * 8 + g;
                uint32_t bh[2] = {Wh[nr * KPP + kb], Wh[nr * KPP + kb + 4]};
                uint32_t bl[2] = {Wl[nr * KPP + kb], Wl[nr * KPP + kb + 4]};
                mma_bf16(acc[nt], ah, bh);
                mma_bf16(acc[nt], ah, bl);
                mma_bf16(acc[nt], al, bh);
            }
        }
    }

    int mo = bm + m0 + g;
    float ts = 0.f, tss = 0.f;
    float rs0 = 0.f, rq0 = 0.f, rs1 = 0.f, rq1 = 0.f;
    if (bn + 64 <= N) {
#pragma unroll
        for (int nt = 0; nt < 4; nt++) {
            int n = bn + wn * 32 + nt * 8 + 2 * t;
            float2 bv = *reinterpret_cast<const float2*>(bias + n);
            size_t o0 = (size_t)mo * ldc + n;
            size_t o1 = (size_t)(mo + 8) * ldc + n;
            float2 r0 = make_float2(acc[nt][0] + bv.x, acc[nt][1] + bv.y);
            float2 r1 = make_float2(acc[nt][2] + bv.x, acc[nt][3] + bv.y);
            if (res) {
                float2 e0 = *reinterpret_cast<const float2*>(res + o0);
                float2 e1 = *reinterpret_cast<const float2*>(res + o1);
                r0.x += e0.x; r0.y += e0.y; r1.x += e1.x; r1.y += e1.y;
            }
            if (gnacc) {
                ts += (r0.x + r0.y) + (r1.x + r1.y);
                tss += r0.x * r0.x + r0.y * r0.y + r1.x * r1.x + r1.y * r1.y;
            }
            if (lnacc) {
                rs0 += r0.x + r0.y;
                rq0 += r0.x * r0.x + r0.y * r0.y;
                rs1 += r1.x + r1.y;
                rq1 += r1.x * r1.x + r1.y * r1.y;
            }
            *reinterpret_cast<float2*>(C + o0) = r0;
            *reinterpret_cast<float2*>(C + o1) = r1;
        }
    } else {
#pragma unroll
        for (int nt = 0; nt < 4; nt++) {
            int n = bn + wn * 32 + nt * 8 + 2 * t;
#pragma unroll
            for (int e = 0; e < 2; e++) {
                if (n + e >= N) continue;
                float v0 = acc[nt][e] + bias[n + e];
                float v1 = acc[nt][2 + e] + bias[n + e];
                if (res) {
                    v0 += res[(size_t)mo * ldc + n + e];
                    v1 += res[(size_t)(mo + 8) * ldc + n + e];
                }
                C[(size_t)mo * ldc + n + e] = v0;
                C[(size_t)(mo + 8) * ldc + n + e] = v1;
            }
        }
    }
    if (lnacc) {
        rs0 += __shfl_xor_sync(0xffffffffu, rs0, 1);
        rs0 += __shfl_xor_sync(0xffffffffu, rs0, 2);
        rq0 += __shfl_xor_sync(0xffffffffu, rq0, 1);
        rq0 += __shfl_xor_sync(0xffffffffu, rq0, 2);
        rs1 += __shfl_xor_sync(0xffffffffu, rs1, 1);
        rs1 += __shfl_xor_sync(0xffffffffu, rs1, 2);
        rq1 += __shfl_xor_sync(0xffffffffu, rq1, 1);
        rq1 += __shfl_xor_sync(0xffffffffu, rq1, 2);
        if (t == 0) {
            atomicAdd(&lnacc[mo * 2], rs0);
            atomicAdd(&lnacc[mo * 2 + 1], rq0);
            atomicAdd(&lnacc[(mo + 8) * 2], rs1);
            atomicAdd(&lnacc[(mo + 8) * 2 + 1], rq1);
        }
    }
    if (gnacc) {
#pragma unroll
        for (int o = 16; o; o >>= 1) {
            ts += __shfl_xor_sync(0xffffffffu, ts, o);
            tss += __shfl_xor_sync(0xffffffffu, tss, o);
        }
        if (!lane) { gsum[wid] = ts; gss2[wid] = tss; }
        __syncthreads();
        if (tid < 2) {
            float S = gsum[tid * 4] + gsum[tid * 4 + 1] + gsum[tid * 4 + 2] + gsum[tid * 4 + 3];
            float SS = gss2[tid * 4] + gss2[tid * 4 + 1] + gss2[tid * 4 + 2] + gss2[tid * 4 + 3];
            int grp = (bn >> 5) + tid;
            atomicAdd(&gnacc[grp * 2], S);
            atomicAdd(&gnacc[grp * 2 + 1], SS);
        }
    }
#undef LOADCHUNK
}

// ---------------- tensor-core flash attention, double-buffered K/V ----------------
// Per-key-half independent online softmax; one __syncthreads per k-tile.
__global__ __launch_bounds__(256) void flash_attn_tc(
        const float* __restrict__ Q, int ldq,
        const float* __restrict__ K, int ldk,
        const float* __restrict__ V, int ldv,
        const float* __restrict__ idkv,
        float* __restrict__ O, int ldo) {
    extern __shared__ uint32_t fs[];
    uint32_t* Qhi = fs + FA_Q;            // [64][20]
    uint32_t* Qlo = Qhi + 1280;
    uint32_t* Khi = fs + FA_K;            // [2][64][20]
    uint32_t* Klo = Khi + 2560;
    uint32_t* Vthi = fs + FA_V;           // [2][32][36]
    uint32_t* Vtlo = Vthi + 2304;
    float* redmax = reinterpret_cast<float*>(fs + FA_RED);
    float* redsum = redmax + 64;
    float* Osm = reinterpret_cast<float*>(fs + FA_OSM);   // [64][33]

    int h = blockIdx.y, q0 = blockIdx.x * BQ;
    int tid = threadIdx.x, wid = tid >> 5, lane = tid & 31;
    int wm = wid & 3, wn = wid >> 2;
    int g = lane >> 2, t = lane & 3;
    int m0 = wm * 16;
    int lrow = tid >> 2, lcol = (tid & 3) * 8;

    // stage Q (scaled, hi/lo split)
    {
        const float* qp = Q + (size_t)(q0 + lrow) * ldq + h * HD + lcol;
        float4 a = *reinterpret_cast<const float4*>(qp);
        float4 b = *reinterpret_cast<const float4*>(qp + 4);
        float xv[8] = {a.x, a.y, a.z, a.w, b.x, b.y, b.z, b.w};
#pragma unroll
        for (int j = 0; j < 4; j++) {
            uint32_t hi, lo;
            split_bf16_pair(xv[2 * j] * SCALE, xv[2 * j + 1] * SCALE, hi, lo);
            Qhi[lrow * 20 + lcol / 2 + j] = hi;
            Qlo[lrow * 20 + lcol / 2 + j] = lo;
        }
    }

    float4 ka, kb, va, vb, ia, ib;
    float kmul;

    auto load_tile = [&](int kt) {
        const float* kp = K + (size_t)(kt + lrow) * ldk + h * HD + lcol;
        const float* vp = V + (size_t)(kt + lrow) * ldv + h * HD + lcol;
        ka = *reinterpret_cast<const float4*>(kp);
        kb = *reinterpret_cast<const float4*>(kp + 4);
        va = *reinterpret_cast<const float4*>(vp);
        vb = *reinterpret_cast<const float4*>(vp + 4);
        kmul = 1.f;
        ia = make_float4(0.f, 0.f, 0.f, 0.f);
        ib = ia;
        if (idkv) {
            const float* ip = idkv + (size_t)(kt + lrow) * 264;
            kmul = 1.f + tanhf(ip[h]);
            ia = *reinterpret_cast<const float4*>(ip + 8 + h * HD + lcol);
            ib = *reinterpret_cast<const float4*>(ip + 8 + h * HD + lcol + 4);
        }
    };

    auto stage_tile = [&](int b) {
        uint32_t* KH = Khi + b * 1280;
        uint32_t* KL = Klo + b * 1280;
        float kv[8] = {ka.x * kmul, ka.y * kmul, ka.z * kmul, ka.w * kmul,
                       kb.x * kmul, kb.y * kmul, kb.z * kmul, kb.w * kmul};
#pragma unroll
        for (int j = 0; j < 4; j++) {
            uint32_t hi, lo;
            split_bf16_pair(kv[2 * j], kv[2 * j + 1], hi, lo);
            KH[lrow * 20 + lcol / 2 + j] = hi;
            KL[lrow * 20 + lcol / 2 + j] = lo;
        }
        float vv[8] = {va.x + ia.x, va.y + ia.y, va.z + ia.z, va.w + ia.w,
                       vb.x + ib.x, vb.y + ib.y, vb.z + ib.z, vb.w + ib.w};
        __nv_bfloat16* VH = reinterpret_cast<__nv_bfloat16*>(Vthi + b * 1152);
        __nv_bfloat16* VL = reinterpret_cast<__nv_bfloat16*>(Vtlo + b * 1152);
#pragma unroll
        for (int j = 0; j < 8; j++) {
            int d = lcol + j;
            float x = vv[j];
            __nv_bfloat16 hb = __float2bfloat16(x);
            VH[d * 72 + lrow] = hb;
            VL[d * 72 + lrow] = __float2bfloat16(x - __bfloat162float(hb));
        }
    };

    float mrow[2] = {-1e30f, -1e30f}, lsum[2] = {0.f, 0.f};
    float Oacc[4][4] = {};

    load_tile(0);
    stage_tile(0);
    __syncthreads();

    const int NT = LQ / BK;   // 25
    for (int it = 0; it < NT; it++) {
        int cur = it & 1;
        if (it + 1 < NT) load_tile((it + 1) * BK);   // global loads in flight

        const uint32_t* KH = Khi + cur * 1280;
        const uint32_t* KL = Klo + cur * 1280;
        const uint32_t* VH = Vthi + cur * 1152;
        const uint32_t* VL = Vtlo + cur * 1152;

        float S[4][4];
#pragma unroll
        for (int nt = 0; nt < 4; nt++)
#pragma unroll
            for (int c = 0; c < 4; c++) S[nt][c] = 0.f;
#pragma unroll
        for (int kc = 0; kc < 2; kc++) {
            uint32_t ah[4], al[4];
            ah[0] = Qhi[(m0 + g) * 20 + kc * 8 + t];
            ah[1] = Qhi[(m0 + 8 + g) * 20 + kc * 8 + t];
            ah[2] = Qhi[(m0 + g) * 20 + kc * 8 + t + 4];
            ah[3] = Qhi[(m0 + 8 + g) * 20 + kc * 8 + t + 4];
            al[0] = Qlo[(m0 + g) * 20 + kc * 8 + t];
            al[1] = Qlo[(m0 + 8 + g) * 20 + kc * 8 + t];
            al[2] = Qlo[(m0 + g) * 20 + kc * 8 + t + 4];
            al[3] = Qlo[(m0 + 8 + g) * 20 + kc * 8 + t + 4];
#pragma unroll
            for (int nt = 0; nt < 4; nt++) {
                int kr = wn * 32 + nt * 8 + g;
                uint32_t bh[2] = {KH[kr * 20 + kc * 8 + t], KH[kr * 20 + kc * 8 + t + 4]};
                uint32_t bl[2] = {KL[kr * 20 + kc * 8 + t], KL[kr * 20 + kc * 8 + t + 4]};
                mma_bf16(S[nt], ah, bh);
                mma_bf16(S[nt], ah, bl);
                mma_bf16(S[nt], al, bh);
            }
        }

        // per-half online softmax (quad shuffles only)
        float pmA = -1e30f, pmB = -1e30f;
#pragma unroll
        for (int nt = 0; nt < 4; nt++) {
            pmA = fmaxf(pmA, fmaxf(S[nt][0], S[nt][1]));
            pmB = fmaxf(pmB, fmaxf(S[nt][2], S[nt][3]));
        }
        pmA = fmaxf(pmA, __shfl_xor_sync(0xffffffffu, pmA, 1));
        pmA = fmaxf(pmA, __shfl_xor_sync(0xffffffffu, pmA, 2));
        pmB = fmaxf(pmB, __shfl_xor_sync(0xffffffffu, pmB, 1));
        pmB = fmaxf(pmB, __shfl_xor_sync(0xffffffffu, pmB, 2));
        float nmA = fmaxf(mrow[0], pmA);
        float nmB = fmaxf(mrow[1], pmB);
        float alA = __expf(mrow[0] - nmA), alB = __expf(mrow[1] - nmB);
        mrow[0] = nmA; mrow[1] = nmB;
        float psA = 0.f, psB = 0.f;
#pragma unroll
        for (int nt = 0; nt < 4; nt++) {
            S[nt][0] = __expf(S[nt][0] - nmA); S[nt][1] = __expf(S[nt][1] - nmA);
            S[nt][2] = __expf(S[nt][2] - nmB); S[nt][3] = __expf(S[nt][3] - nmB);
            psA += S[nt][0] + S[nt][1];
            psB += S[nt][2] + S[nt][3];
        }
        psA += __shfl_xor_sync(0xffffffffu, psA, 1);
        psA += __shfl_xor_sync(0xffffffffu, psA, 2);
        psB += __shfl_xor_sync(0xffffffffu, psB, 1);
        psB += __shfl_xor_sync(0xffffffffu, psB, 2);
        lsum[0] = lsum[0] * alA + psA;
        lsum[1] = lsum[1] * alB + psB;
#pragma unroll
        for (int nt = 0; nt < 4; nt++) {
            Oacc[nt][0] *= alA; Oacc[nt][1] *= alA;
            Oacc[nt][2] *= alB; Oacc[nt][3] *= alB;
        }

        // PV
#pragma unroll
        for (int kc2 = 0; kc2 < 2; kc2++) {
            uint32_t ph[4], pl[4];
            split_bf16_pair(S[2 * kc2][0], S[2 * kc2][1], ph[0], pl[0]);
            split_bf16_pair(S[2 * kc2][2], S[2 * kc2][3], ph[1], pl[1]);
            split_bf16_pair(S[2 * kc2 + 1][0], S[2 * kc2 + 1][1], ph[2], pl[2]);
            split_bf16_pair(S[2 * kc2 + 1][2], S[2 * kc2 + 1][3], ph[3], pl[3]);
            int cb = wn * 16 + kc2 * 8 + t;
#pragma unroll
            for (int ntv = 0; ntv < 4; ntv++) {
                int vr = ntv * 8 + g;
                uint32_t bh[2] = {VH[vr * 36 + cb], VH[vr * 36 + cb + 4]};
                uint32_t bl[2] = {VL[vr * 36 + cb], VL[vr * 36 + cb + 4]};
                mma_bf16(Oacc[ntv], ph, bh);
                mma_bf16(Oacc[ntv], ph, bl);
                mma_bf16(Oacc[ntv], pl, bh);
            }
        }

        if (it + 1 < NT) {
            stage_tile((it + 1) & 1);
            __syncthreads();
        }
    }

    // epilogue: merge the two key-halves (exact logsumexp combine)
    __syncthreads();
    if (wn == 0) {
#pragma unroll
        for (int ntv = 0; ntv < 4; ntv++) {
            int d = ntv * 8 + 2 * t;
            Osm[(m0 + g) * 33 + d] = Oacc[ntv][0];
            Osm[(m0 + g) * 33 + d + 1] = Oacc[ntv][1];
            Osm[(m0 + 8 + g) * 33 + d] = Oacc[ntv][2];
            Osm[(m0 + 8 + g) * 33 + d + 1] = Oacc[ntv][3];
        }
        if (t == 0) {
            redmax[m0 + g] = mrow[0];
            redsum[m0 + g] = lsum[0];
            redmax[m0 + 8 + g] = mrow[1];
            redsum[m0 + 8 + g] = lsum[1];
        }
    }
    __syncthreads();
    if (wn == 1) {
        float mA0 = redmax[m0 + g], lA0 = redsum[m0 + g];
        float mB0 = redmax[m0 + 8 + g], lB0 = redsum[m0 + 8 + g];
        float MA = fmaxf(mA0, mrow[0]), MB = fmaxf(mB0, mrow[1]);
        float eA0 = __expf(mA0 - MA), eA1 = __expf(mrow[0] - MA);
        float eB0 = __expf(mB0 - MB), eB1 = __expf(mrow[1] - MB);
        float invA = 1.0f / (lA0 * eA0 + lsum[0] * eA1);
        float invB = 1.0f / (lB0 * eB0 + lsum[1] * eB1);
#pragma unroll
        for (int ntv = 0; ntv < 4; ntv++) {
            int d = ntv * 8 + 2 * t;
            float* op0 = O + (size_t)(q0 + m0 + g) * ldo + h * HD + d;
            float* op1 = O + (size_t)(q0 + m0 + 8 + g) * ldo + h * HD + d;
            op0[0] = (Osm[(m0 + g) * 33 + d] * eA0 + Oacc[ntv][0] * eA1) * invA;
            op0[1] = (Osm[(m0 + g) * 33 + d + 1] * eA0 + Oacc[ntv][1] * eA1) * invA;
            op1[0] = (Osm[(m0 + 8 + g) * 33 + d] * eB0 + Oacc[ntv][2] * eB1) * invB;
            op1[1] = (Osm[(m0 + 8 + g) * 33 + d + 1] * eB0 + Oacc[ntv][3] * eB1) * invB;
        }
    }
}

// ---------------- tiled local attention with fused global-KV transform ----------------
__global__ __launch_bounds__(256) void local_attn_tile(
        const float* __restrict__ Q, int ldq,
        const float* __restrict__ qvbuf, const float* __restrict__ idkv,
        float* __restrict__ O, int ldo) {
    extern __shared__ float sm[];
    float* winK = sm;
    float* winV = sm + LTWW * 33;
    float* pb = sm + 2 * LTWW * 33;
    int h = blockIdx.y;
    int ty0 = (blockIdx.x / 5) * 8, tx0 = (blockIdx.x % 5) * 8;
    int wy0 = ty0 - PADR, wx0 = tx0 - PADR;
    int tid = threadIdx.x, w = tid >> 5, lane = tid & 31;

    for (int idx = tid; idx < LTWW * 32; idx += 256) {
        int pos = idx >> 5, d = idx & 31;
        int gy = wy0 + pos / LTW, gx = wx0 + pos % LTW;
        bool ok = ((unsigned)gy < H2D) && ((unsigned)gx < W2D);
        float kvv = 0.f, vvv = 0.f;
        if (ok) {
            size_t r = (size_t)(gy * W2D + gx);
            float ik = idkv[r * 264 + h];
            kvv = qvbuf[r * 512 + h * HD + d] * (1.0f + tanhf(ik));
            vvv = qvbuf[r * 512 + 256 + h * HD + d] + idkv[r * 264 + 8 + h * HD + d];
        }
        winK[pos * 33 + d] = kvv;
        winV[pos * 33 + d] = vvv;
    }
    __syncthreads();

    int qy = ty0 + w;
    for (int qi = 0; qi < 8; qi++) {
        int qx = tx0 + qi;
        float qv = Q[(size_t)(qy * W2D + qx) * ldq + h * HD + lane] * SCALE;
        float lg[8];
        int wi[8];
        bool val[8];
#pragma unroll
        for (int c = 0; c < 8; c++) {
            int j = c * 32 + lane;
            int jr = j / 15, jc = j - jr * 15;
            int gy2 = qy + jr - PADR, gx2 = qx + jc - PADR;
            val[c] = (j < WSQ) && ((unsigned)gy2 < H2D) && ((unsigned)gx2 < W2D);
            wi[c] = (j < WSQ) ? ((w + jr) * LTW + (qi + jc)) : 0;
            lg[c] = 0.f;
        }
#pragma unroll 8
        for (int d = 0; d < 32; d++) {
            float qd = __shfl_sync(0xffffffffu, qv, d);
#pragma unroll
            for (int c = 0; c < 8; c++)
                lg[c] = fmaf(qd, winK[wi[c] * 33 + d], lg[c]);
        }
        float mx = -1e30f;
#pragma unroll
        for (int c = 0; c < 8; c++) {
            lg[c] = val[c] ? lg[c] : -1e30f;
            mx = fmaxf(mx, lg[c]);
        }
#pragma unroll
        for (int o = 16; o; o >>= 1) mx = fmaxf(mx, __shfl_xor_sync(0xffffffffu, mx, o));
        float s = 0.f;
#pragma unroll
        for (int c = 0; c < 8; c++) {
            lg[c] = __expf(lg[c] - mx);
            s += lg[c];
        }
#pragma unroll
        for (int o = 16; o; o >>= 1) s += __shfl_xor_sync(0xffffffffu, s, o);
        float inv = 1.0f / s;
#pragma unroll
        for (int c = 0; c < 8; c++) pb[w * 264 + c * 32 + lane] = lg[c] * inv;
        __syncwarp();

        float oacc = 0.f;
        int j = 0;
#pragma unroll
        for (int jr = 0; jr < 15; jr++) {
            int base = ((w + jr) * LTW + qi) * 33 + lane;
#pragma unroll
            for (int jc = 0; jc < 15; jc++) {
                oacc = fmaf(pb[w * 264 + j], winV[base + jc * 33], oacc);
                j++;
            }
        }
        O[(size_t)(qy * W2D + qx) * ldo + h * HD + lane] = oacc;
        __syncwarp();
    }
}

// ---------------- fused GN-apply + GELU + depthwise 5x5 conv ----------------
#define DWP 144
__global__ __launch_bounds__(256) void dwconv_gn(
        const float* __restrict__ x1, const float* __restrict__ acc,
        const float* __restrict__ gg, const float* __restrict__ gb,
        const float* __restrict__ dwk, float* __restrict__ y) {
    extern __shared__ float sm[];
    float* winX = sm;
    float* wk = sm + DWP * 128;
    float* sgg = wk + 128 * 25;
    float* sgb = sgg + 128;
    float* smr = sgb + 128;
    int tile = blockIdx.x, slab = blockIdx.y;
    int ty0 = (tile / 5) * 8, tx0 = (tile % 5) * 8;
    int tid = threadIdx.x;
    int c0 = slab * 128;

    if (tid < 4) {
        int gidx = (c0 >> 5) + tid;
        const float inv = 1.0f / 51200.0f;
        float s = acc[gidx * 2], ss = acc[gidx * 2 + 1];
        float m = s * inv;
        float var = ss * inv - m * m;
        smr[tid] = m;
        smr[4 + tid] = rsqrtf(var + 1e-5f);
    }
    if (tid < 128) {
        sgg[tid] = gg[c0 + tid];
        sgb[tid] = gb[c0 + tid];
    }
    for (int i = tid; i < 128 * 25; i += 256) wk[i] = dwk[c0 * 25 + i];
    __syncthreads();

    for (int idx = tid; idx < DWP * 32; idx += 256) {
        int pos = idx >> 5, f4 = idx & 31;
        int gy = ty0 - 2 + pos / 12, gx = tx0 - 2 + pos % 12;
        bool ok = ((unsigned)gy < H2D) && ((unsigned)gx < W2D);
        float4 v = ok ? *reinterpret_cast<const float4*>(
                            x1 + (size_t)(gy * W2D + gx) * DFF + c0 + f4 * 4)
                      : make_float4(0.f, 0.f, 0.f, 0.f);
        int grp = f4 >> 3;
        float m = smr[grp], r = smr[4 + grp];
        int cl = f4 * 4;
        float e[4] = {v.x, v.y, v.z, v.w};
#pragma unroll
        for (int j = 0; j < 4; j++) {
            float t2 = (e[j] - m) * r * sgg[cl + j] + sgb[cl + j];
            e[j] = 0.5f * t2 * (1.0f + erff(t2 * 0.70710678118654752f));
        }
        float4 o = make_float4(ok ? e[0] : 0.f, ok ? e[1] : 0.f,
                               ok ? e[2] : 0.f, ok ? e[3] : 0.f);
        *reinterpret_cast<float4*>(&winX[pos * 128 + cl]) = o;
    }
    __syncthreads();

    int c = tid & 127, pg = tid >> 7;
    float wreg[25];
#pragma unroll
    for (int k = 0; k < 25; k++) wreg[k] = wk[c * 25 + k];

#pragma unroll
    for (int py = 0; py < 4; py++) {
        int oy = pg * 4 + py;
        float oac[8] = {};
#pragma unroll
        for (int dy = 0; dy < 5; dy++) {
            float rv[12];
            int rb = (oy + dy) * 12;
#pragma unroll
            for (int j = 0; j < 12; j++) rv[j] = winX[(rb + j) * 128 + c];
#pragma unroll
            for (int dx = 0; dx < 5; dx++) {
                float wv = wreg[dy * 5 + dx];
#pragma unroll
                for (int o = 0; o < 8; o++)
                    oac[o] = fmaf(rv[o + dx], wv, oac[o]);
            }
        }
#pragma unroll
        for (int o = 0; o < 8; o++)
            y[(size_t)((ty0 + oy) * W2D + tx0 + o) * DFF + c0 + c] = oac[o];
    }
}

// ---------------- host ----------------
static const int GEMM_SMEM = 4 * GSEG * (int)sizeof(uint32_t);
static const int FLASH_SMEM = FA_TOT * (int)sizeof(uint32_t);   // 58,112 B
static const int DW_SMEM = (DWP * 128 + 128 * 25 + 256 + 8) * (int)sizeof(float);

extern "C" void kernel_launch(void* const* d_in, const int* in_sizes, int n_in,
                              void* d_out, int out_size) {
    const float* tgt = (const float*)d_in[0];
    const float* curr_id_emb = (const float*)d_in[1];
    const float* self_pos = (const float*)d_in[2];
    const float* ln1_g = (const float*)d_in[3];
    const float* ln1_b = (const float*)d_in[4];
    const float* sa_wq = (const float*)d_in[5];
    const float* sa_bq = (const float*)d_in[6];
    const float* sa_wk = (const float*)d_in[7];
    const float* sa_bk = (const float*)d_in[8];
    const float* sa_wv = (const float*)d_in[9];
    const float* sa_bv = (const float*)d_in[10];
    const float* sa_wo = (const float*)d_in[11];
    const float* sa_bo = (const float*)d_in[12];
    const float* ln2_g = (const float*)d_in[13];
    const float* ln2_b = (const float*)d_in[14];
    const float* w_qv = (const float*)d_in[15];
    const float* b_qv = (const float*)d_in[16];
    const float* w_id = (const float*)d_in[17];
    const float* b_id = (const float*)d_in[18];
    const float* lt_wo = (const float*)d_in[19];
    const float* lt_bo = (const float*)d_in[20];
    const float* st_wo = (const float*)d_in[21];
    const float* st_bo = (const float*)d_in[22];
    const float* ln3_g = (const float*)d_in[23];
    const float* ln3_b = (const float*)d_in[24];
    const float* w1 = (const float*)d_in[25];
    const float* b1 = (const float*)d_in[26];
    const float* gn_g = (const float*)d_in[27];
    const float* gn_b = (const float*)d_in[28];
    const float* dw_k = (const float*)d_in[29];
    const float* w2 = (const float*)d_in[30];
    const float* b2 = (const float*)d_in[31];
    float* out = (float*)d_out;

    float *qkv, *cat, *tgt1, *qv, *idkv, *tgt2, *x1, *x2, *gnacc;
    float *ln1acc, *ln2acc, *ln3acc, *bqkv, *bltst;
    uint32_t *whi, *wlo;
    cudaGetSymbolAddress((void**)&qkv, g_qkv);
    cudaGetSymbolAddress((void**)&cat, g_cat);
    cudaGetSymbolAddress((void**)&tgt1, g_tgt1);
    cudaGetSymbolAddress((void**)&qv, g_qv);
    cudaGetSymbolAddress((void**)&idkv, g_idkv);
    cudaGetSymbolAddress((void**)&tgt2, g_tgt2);
    cudaGetSymbolAddress((void**)&x1, g_x1);
    cudaGetSymbolAddress((void**)&x2, g_x2);
    cudaGetSymbolAddress((void**)&gnacc, g_gnacc);
    cudaGetSymbolAddress((void**)&ln1acc, g_ln1acc);
    cudaGetSymbolAddress((void**)&ln2acc, g_ln2acc);
    cudaGetSymbolAddress((void**)&ln3acc, g_ln3acc);
    cudaGetSymbolAddress((void**)&bqkv, g_bqkv);
    cudaGetSymbolAddress((void**)&bltst, g_bltst);
    cudaGetSymbolAddress((void**)&whi, g_whi);
    cudaGetSymbolAddress((void**)&wlo, g_wlo);

    const int LOCAL_SMEM = (2 * LTWW * 33 + 8 * 264) * (int)sizeof(float);

    static bool init = false;
    static cudaStream_t s1, s2;
    static cudaEvent_t evR, evW, evB, evL1, evV, evQV, evL;
    if (!init) {
        cudaStreamCreateWithFlags(&s1, cudaStreamNonBlocking);
        cudaStreamCreateWithFlags(&s2, cudaStreamNonBlocking);
        cudaEventCreateWithFlags(&evR, cudaEventDisableTiming);
        cudaEventCreateWithFlags(&evW, cudaEventDisableTiming);
        cudaEventCreateWithFlags(&evB, cudaEventDisableTiming);
        cudaEventCreateWithFlags(&evL1, cudaEventDisableTiming);
        cudaEventCreateWithFlags(&evV, cudaEventDisableTiming);
        cudaEventCreateWithFlags(&evQV, cudaEventDisableTiming);
        cudaEventCreateWithFlags(&evL, cudaEventDisableTiming);
        cudaFuncSetAttribute(local_attn_tile, cudaFuncAttributeMaxDynamicSharedMemorySize, LOCAL_SMEM);
        cudaFuncSetAttribute(gemm_tc2, cudaFuncAttributeMaxDynamicSharedMemorySize, GEMM_SMEM);
        cudaFuncSetAttribute(flash_attn_tc, cudaFuncAttributeMaxDynamicSharedMemorySize, FLASH_SMEM);
        cudaFuncSetAttribute(dwconv_gn, cudaFuncAttributeMaxDynamicSharedMemorySize, DW_SMEM);
        init = true;
    }

    auto GEMM = [&](cudaStream_t st, const float* A, int lda, int woff, const float* bias,
                    const float* res, float* C, int ldc, int M, int N, int K, float* gn,
                    float* lnacc, const float* lnst, const float* lng, const float* lnb,
                    const float* posp) {
        dim3 grid((N + 63) / 64, (M + 63) / 64);
        gemm_tc2<<<grid, 256, GEMM_SMEM, st>>>(A, lda, whi + woff, wlo + woff, bias, res, C,
                                               ldc, M, N, K, gn, lnacc, lnst, lng, lnb, posp);
    };

    // ---- fork: side stream does weight conversion + idkv GEMM ----
    cudaEventRecord(evR, 0);
    cudaStreamWaitEvent(s1, evR, 0);
    conv_weights<<<(TOTPAIRS + 255) / 256, 256, 0, s1>>>(
        sa_wq, sa_wk, sa_wv, sa_wo, w_qv, w_id, lt_wo, st_wo, w1, w2,
        sa_bq, sa_bk, sa_bv, lt_bo, st_bo);
    cudaEventRecord(evW, s1);
    GEMM(s1, curr_id_emb, CD, OFF_WID, b_id, nullptr, idkv, 264, LQ, 264, CD,
         nullptr, nullptr, nullptr, nullptr, nullptr, nullptr);
    cudaEventRecord(evB, s1);

    // ---- self-attention block: qk GEMM (stream 0) || v GEMM (s2), packed qkv ----
    row_stats<<<LQ / 8, 256>>>(tgt, ln1acc);
    cudaEventRecord(evL1, 0);
    cudaStreamWaitEvent(0, evW, 0);
    GEMM(0, tgt, CD, OFF_QKV, bqkv, nullptr, qkv, 768, LQ, 512, CD,
         nullptr, nullptr, ln1acc, ln1_g, ln1_b, self_pos);                  // [q|k]
    cudaStreamWaitEvent(s2, evW, 0);
    cudaStreamWaitEvent(s2, evL1, 0);
    GEMM(s2, tgt, CD, OFF_QKV + 65536, bqkv + 512, nullptr, qkv + 512, 768, LQ, CD, CD,
         nullptr, nullptr, ln1acc, ln1_g, ln1_b, nullptr);                   // v (parallel)
    cudaEventRecord(evV, s2);
    cudaStreamWaitEvent(0, evV, 0);
    flash_attn_tc<<<dim3(LQ / BQ, NH), 256, FLASH_SMEM>>>(
        qkv, 768, qkv + 256, 768, qkv + 512, 768, nullptr, cat, 512);
    GEMM(0, cat, 512, OFF_WO, sa_bo, tgt, tgt1, 256, LQ, CD, CD,
         nullptr, ln2acc, nullptr, nullptr, nullptr, nullptr);   // tgt1 = tgt + SA, +ln2 stats

    // ---- long/short-term block (ln2 applied inline in qv GEMM A-staging) ----
    GEMM(0, tgt1, CD, OFF_WQV, b_qv, nullptr, qv, 512, LQ, 512, CD,
         nullptr, nullptr, ln2acc, ln2_g, ln2_b, nullptr);                   // [curr_Q|curr_V]
    cudaEventRecord(evQV, 0);
    cudaStreamWaitEvent(s2, evQV, 0);
    cudaStreamWaitEvent(s2, evB, 0);
    local_attn_tile<<<dim3(25, NH), 256, LOCAL_SMEM, s2>>>(qv, 512, qv, idkv, cat + 256, 512);
    cudaEventRecord(evL, s2);
    cudaStreamWaitEvent(0, evB, 0);
    flash_attn_tc<<<dim3(LQ / BQ, NH), 256, FLASH_SMEM>>>(
        qv, 512, qv, 512, qv + 256, 512, idkv, cat, 512);
    cudaStreamWaitEvent(0, evL, 0);
    GEMM(0, cat, 512, OFF_LTST, bltst, tgt1, tgt2, 256, LQ, CD, 512,
         nullptr, ln3acc, nullptr, nullptr, nullptr, nullptr);  // tgt2 = tgt1+LT+ST, +ln3 stats

    // ---- FFN block (ln3 applied inline in w1 GEMM A-staging) ----
    GEMM(0, tgt2, CD, OFF_W1, b1, nullptr, x1, DFF, LQ, DFF, CD,
         gnacc, nullptr, ln3acc, ln3_g, ln3_b, nullptr);                     // + fused GN stats
    dwconv_gn<<<dim3(25, 8), 256, DW_SMEM>>>(x1, gnacc, gn_g, gn_b, dw_k, x2);
    GEMM(0, x2, DFF, OFF_W2, b2, tgt2, out, 256, LQ, CD, DFF,
         nullptr, nullptr, nullptr, nullptr, nullptr, nullptr);              // out = tgt2 + FFN
}